// round 1
// baseline (speedup 1.0000x reference)
#include <cuda_runtime.h>
#include <math.h>

#define S_LEN  2048
#define DMODEL 1024
#define NH     16
#define DK     64
#define BATCH  4
#define M_TOT  (BATCH * S_LEN)   // 8192

// Scratch (static __device__ — no allocations allowed)
__device__ float g_Q[BATCH * NH * S_LEN * DK];   // [b,h,s,d]
__device__ float g_K[BATCH * NH * S_LEN * DK];
__device__ float g_V[BATCH * NH * S_LEN * DK];
__device__ float g_AO[(size_t)M_TOT * DMODEL];   // attention out, [m][e] row-major

// ---------------------------------------------------------------------------
// GEMM: Y = X @ W^T + bias.  X:[M,K] row-major, W:[N,K] row-major.
// M=8192, N=K=1024. Block tile 64x64, BK=16, 256 threads, 4x4 per thread.
// mode 0: scatter output into [b,h,s,d] head layout (n-tile == one head)
// mode 1: plain [m][n] row-major output
// ---------------------------------------------------------------------------
__global__ __launch_bounds__(256) void gemm_bias_kernel(
    const float* __restrict__ X, const float* __restrict__ W,
    const float* __restrict__ bias, float* __restrict__ Y, int mode)
{
    __shared__ __align__(16) float As[16][68];  // [k][m] k-major
    __shared__ __align__(16) float Bs[16][68];  // [k][n] k-major

    const int tid = threadIdx.x;
    const int tx = tid & 15;      // n micro index
    const int ty = tid >> 4;      // m micro index
    const int m0 = blockIdx.y * 64;
    const int n0 = blockIdx.x * 64;

    const int lr = tid >> 2;          // 0..63 tile row
    const int lc = (tid & 3) * 4;     // 0,4,8,12 k-col

    const float* Xp = X + (size_t)(m0 + lr) * DMODEL + lc;
    const float* Wp = W + (size_t)(n0 + lr) * DMODEL + lc;

    float acc[4][4] = {};

    for (int k0 = 0; k0 < DMODEL; k0 += 16) {
        float4 a = *(const float4*)(Xp + k0);
        float4 b = *(const float4*)(Wp + k0);
        __syncthreads();   // prior iteration's smem reads complete
        As[lc + 0][lr] = a.x; As[lc + 1][lr] = a.y;
        As[lc + 2][lr] = a.z; As[lc + 3][lr] = a.w;
        Bs[lc + 0][lr] = b.x; Bs[lc + 1][lr] = b.y;
        Bs[lc + 2][lr] = b.z; Bs[lc + 3][lr] = b.w;
        __syncthreads();

        #pragma unroll
        for (int kk = 0; kk < 16; kk++) {
            float4 ra = *(const float4*)&As[kk][ty * 4];
            float4 rb = *(const float4*)&Bs[kk][tx * 4];
            float av[4] = {ra.x, ra.y, ra.z, ra.w};
            float bv[4] = {rb.x, rb.y, rb.z, rb.w};
            #pragma unroll
            for (int i = 0; i < 4; i++)
                #pragma unroll
                for (int j = 0; j < 4; j++)
                    acc[i][j] = fmaf(av[i], bv[j], acc[i][j]);
        }
    }

    const int n = n0 + tx * 4;
    float4 bb = *(const float4*)&bias[n];
    const int h = n0 >> 6;   // mode 0: tile spans exactly one head

    #pragma unroll
    for (int i = 0; i < 4; i++) {
        const int m = m0 + ty * 4 + i;
        float4 r;
        r.x = acc[i][0] + bb.x;
        r.y = acc[i][1] + bb.y;
        r.z = acc[i][2] + bb.z;
        r.w = acc[i][3] + bb.w;
        if (mode == 0) {
            const int b = m >> 11;        // /2048
            const int s = m & 2047;
            size_t idx = (((size_t)(b * NH + h) * S_LEN + s) * DK) + (size_t)(tx * 4);
            *(float4*)&Y[idx] = r;
        } else {
            *(float4*)&Y[(size_t)m * DMODEL + n] = r;
        }
    }
}

// ---------------------------------------------------------------------------
// Flash attention: per (b,h), q-tile of 64 rows, streaming k-tiles of 64.
// smem: Qt[d][i] (k-major Q), KP = union{ Kt[d][j], P[i][j] }, Vs[j][e].
// Exactly 48 KB static smem -> 4 CTAs/SM.
// ---------------------------------------------------------------------------
__global__ __launch_bounds__(256) void attn_kernel(float* __restrict__ AO)
{
    __shared__ __align__(16) float Qt[64][64];   // [d][i]
    __shared__ __align__(16) float KP[64][64];   // Kt[d][j] then P[i][j]
    __shared__ __align__(16) float Vs[64][64];   // [j][e]

    const int tid = threadIdx.x;
    const int tx = tid & 15;
    const int ty = tid >> 4;
    const int q0 = blockIdx.x * 64;
    const int bh = blockIdx.y;

    const float* Qg = g_Q + (size_t)bh * S_LEN * DK;
    const float* Kg = g_K + (size_t)bh * S_LEN * DK;
    const float* Vg = g_V + (size_t)bh * S_LEN * DK;

    const int lr = tid >> 2;            // 0..63
    const int lc = (tid & 3) * 16;      // 0,16,32,48

    // Load Q tile, transposed to k-major
    {
        const float* p = Qg + (size_t)(q0 + lr) * DK + lc;
        #pragma unroll
        for (int i = 0; i < 4; i++) {
            float4 v = *(const float4*)(p + i * 4);
            Qt[lc + i * 4 + 0][lr] = v.x;
            Qt[lc + i * 4 + 1][lr] = v.y;
            Qt[lc + i * 4 + 2][lr] = v.z;
            Qt[lc + i * 4 + 3][lr] = v.w;
        }
    }

    float acc[4][4] = {};
    float mrow[4], lrow[4];
    #pragma unroll
    for (int i = 0; i < 4; i++) { mrow[i] = -1e30f; lrow[i] = 0.f; }

    for (int j0 = 0; j0 < S_LEN; j0 += 64) {
        // stage K (transposed) and V (row-major) tiles
        const float* kp = Kg + (size_t)(j0 + lr) * DK + lc;
        const float* vp = Vg + (size_t)(j0 + lr) * DK + lc;
        float4 kv[4], vv[4];
        #pragma unroll
        for (int i = 0; i < 4; i++) {
            kv[i] = *(const float4*)(kp + i * 4);
            vv[i] = *(const float4*)(vp + i * 4);
        }
        __syncthreads();   // prev iteration's PV reads (KP, Vs) done
        #pragma unroll
        for (int i = 0; i < 4; i++) {
            KP[lc + i * 4 + 0][lr] = kv[i].x;
            KP[lc + i * 4 + 1][lr] = kv[i].y;
            KP[lc + i * 4 + 2][lr] = kv[i].z;
            KP[lc + i * 4 + 3][lr] = kv[i].w;
            *(float4*)&Vs[lr][lc + i * 4] = vv[i];
        }
        __syncthreads();   // tiles ready (also covers Qt on first iter)

        // scores: S = Q K^T * (1/8)
        float s[4][4] = {};
        #pragma unroll
        for (int d = 0; d < 64; d++) {
            float4 ra = *(const float4*)&Qt[d][ty * 4];
            float4 rb = *(const float4*)&KP[d][tx * 4];
            float av[4] = {ra.x, ra.y, ra.z, ra.w};
            float bv[4] = {rb.x, rb.y, rb.z, rb.w};
            #pragma unroll
            for (int i = 0; i < 4; i++)
                #pragma unroll
                for (int j = 0; j < 4; j++)
                    s[i][j] = fmaf(av[i], bv[j], s[i][j]);
        }

        // online softmax per row (rows owned across 16 tx lanes)
        #pragma unroll
        for (int i = 0; i < 4; i++) {
            #pragma unroll
            for (int j = 0; j < 4; j++) s[i][j] *= 0.125f;
            float mx = fmaxf(fmaxf(s[i][0], s[i][1]), fmaxf(s[i][2], s[i][3]));
            mx = fmaxf(mx, __shfl_xor_sync(0xffffffffu, mx, 1));
            mx = fmaxf(mx, __shfl_xor_sync(0xffffffffu, mx, 2));
            mx = fmaxf(mx, __shfl_xor_sync(0xffffffffu, mx, 4));
            mx = fmaxf(mx, __shfl_xor_sync(0xffffffffu, mx, 8));
            float mnew = fmaxf(mrow[i], mx);
            float alpha = __expf(mrow[i] - mnew);
            mrow[i] = mnew;
            float rs = 0.f;
            #pragma unroll
            for (int j = 0; j < 4; j++) {
                s[i][j] = __expf(s[i][j] - mnew);
                rs += s[i][j];
            }
            rs += __shfl_xor_sync(0xffffffffu, rs, 1);
            rs += __shfl_xor_sync(0xffffffffu, rs, 2);
            rs += __shfl_xor_sync(0xffffffffu, rs, 4);
            rs += __shfl_xor_sync(0xffffffffu, rs, 8);
            lrow[i] = lrow[i] * alpha + rs;
            #pragma unroll
            for (int j = 0; j < 4; j++) acc[i][j] *= alpha;
        }

        __syncthreads();   // all score reads of KP (=Kt) done
        // store P into KP as [i][j]
        #pragma unroll
        for (int i = 0; i < 4; i++)
            *(float4*)&KP[ty * 4 + i][tx * 4] =
                make_float4(s[i][0], s[i][1], s[i][2], s[i][3]);
        __syncthreads();

        // O += P @ V
        #pragma unroll
        for (int j = 0; j < 64; j++) {
            float4 rv = *(const float4*)&Vs[j][tx * 4];
            float bv[4] = {rv.x, rv.y, rv.z, rv.w};
            float pv[4];
            #pragma unroll
            for (int i = 0; i < 4; i++) pv[i] = KP[ty * 4 + i][j];
            #pragma unroll
            for (int i = 0; i < 4; i++)
                #pragma unroll
                for (int e = 0; e < 4; e++)
                    acc[i][e] = fmaf(pv[i], bv[e], acc[i][e]);
        }
    }

    // epilogue: AO[b*S + s][h*64 + e] = acc / l
    const int h = bh & (NH - 1);
    const int b = bh >> 4;
    #pragma unroll
    for (int i = 0; i < 4; i++) {
        const int srow = q0 + ty * 4 + i;
        const float inv = 1.0f / lrow[i];
        float4 r = make_float4(acc[i][0] * inv, acc[i][1] * inv,
                               acc[i][2] * inv, acc[i][3] * inv);
        size_t idx = ((size_t)(b * S_LEN + srow) * DMODEL) + (size_t)(h * DK + tx * 4);
        *(float4*)&AO[idx] = r;
    }
}

// ---------------------------------------------------------------------------
extern "C" void kernel_launch(void* const* d_in, const int* in_sizes, int n_in,
                              void* d_out, int out_size)
{
    (void)in_sizes; (void)n_in; (void)out_size;
    const float* q  = (const float*)d_in[0];
    const float* k  = (const float*)d_in[1];
    const float* v  = (const float*)d_in[2];
    const float* Wq = (const float*)d_in[3];
    const float* bq = (const float*)d_in[4];
    const float* Wk = (const float*)d_in[5];
    const float* bk = (const float*)d_in[6];
    const float* Wv = (const float*)d_in[7];
    const float* bv = (const float*)d_in[8];
    const float* Wo = (const float*)d_in[9];
    const float* bo = (const float*)d_in[10];
    float* out = (float*)d_out;

    float *Qp, *Kp, *Vp, *AOp;
    cudaGetSymbolAddress((void**)&Qp,  g_Q);
    cudaGetSymbolAddress((void**)&Kp,  g_K);
    cudaGetSymbolAddress((void**)&Vp,  g_V);
    cudaGetSymbolAddress((void**)&AOp, g_AO);

    dim3 ggrid(DMODEL / 64, M_TOT / 64);   // (16, 128)
    gemm_bias_kernel<<<ggrid, 256>>>(q, Wq, bq, Qp, 0);
    gemm_bias_kernel<<<ggrid, 256>>>(k, Wk, bk, Kp, 0);
    gemm_bias_kernel<<<ggrid, 256>>>(v, Wv, bv, Vp, 0);

    attn_kernel<<<dim3(S_LEN / 64, BATCH * NH), 256>>>(AOp);

    gemm_bias_kernel<<<ggrid, 256>>>(AOp, Wo, bo, out, 1);
}

// round 5
// speedup vs baseline: 1.4145x; 1.4145x over previous
#include <cuda_runtime.h>
#include <cstdint>
#include <math.h>

#define S_LEN  2048
#define DMODEL 1024
#define NH     16
#define DK     64
#define BATCH  4
#define M_TOT  (BATCH * S_LEN)   // 8192

// Scratch (static __device__ — no allocations allowed)
__device__ float g_Q[BATCH * NH * S_LEN * DK];   // [b,h,s,d]
__device__ float g_K[BATCH * NH * S_LEN * DK];
__device__ float g_V[BATCH * NH * S_LEN * DK];
__device__ float g_AO[(size_t)M_TOT * DMODEL];   // attention out, [m][e] row-major

// ---------------------------------------------------------------------------
__device__ __forceinline__ float tf32_rn(float x) {
    uint32_t u;
    asm("cvt.rna.tf32.f32 %0, %1;" : "=r"(u) : "f"(x));
    return __uint_as_float(u);
}

// m16n8k8 tf32 mma: D += A*B. A row-major 16x8, B[k][n] (col), C/D fp32.
__device__ __forceinline__ void mma16n8k8(float* d, const float* a, const float* b) {
    asm volatile(
        "mma.sync.aligned.m16n8k8.row.col.f32.tf32.tf32.f32 "
        "{%0,%1,%2,%3}, {%4,%5,%6,%7}, {%8,%9}, {%0,%1,%2,%3};"
        : "+f"(d[0]), "+f"(d[1]), "+f"(d[2]), "+f"(d[3])
        : "r"(__float_as_uint(a[0])), "r"(__float_as_uint(a[1])),
          "r"(__float_as_uint(a[2])), "r"(__float_as_uint(a[3])),
          "r"(__float_as_uint(b[0])), "r"(__float_as_uint(b[1])));
}

// ---------------------------------------------------------------------------
// Tensor-core GEMM: Y = X @ W^T + bias.  X:[M,1024] rm, W:[1024,1024] rm.
// CTA 128x128, 8 warps (2m x 4n), warp tile 64x32, BK=16.
// tf32 RN rounding folded into smem staging (unbiased tensor math).
// mode 0: scatter into [b,h,s,d] head layout; mode 1: [m][n] row-major.
// ---------------------------------------------------------------------------
__global__ __launch_bounds__(256, 2) void gemm_mma_kernel(
    const float* __restrict__ X, const float* __restrict__ W,
    const float* __restrict__ bias, float* __restrict__ Y, int mode)
{
    __shared__ __align__(16) float As[128][20];   // [m][k], stride 20 -> conflict-free frags
    __shared__ __align__(16) float Bs[128][20];   // [n][k]

    const int tid  = threadIdx.x;
    const int lane = tid & 31;
    const int wid  = tid >> 5;
    const int g = lane >> 2;          // 0..7
    const int t = lane & 3;           // 0..3
    const int wm = (wid >> 2) * 64;   // warp m offset: 0,64
    const int wn = (wid & 3) * 32;    // warp n offset: 0..96
    const int m0 = blockIdx.y * 128;
    const int n0 = blockIdx.x * 128;

    // staging: each thread loads 8 contiguous floats (row tid/2, half tid&1)
    const int srow = tid >> 1;
    const int scol = (tid & 1) * 8;
    const float* Xp = X + (size_t)(m0 + srow) * DMODEL + scol;
    const float* Wp = W + (size_t)(n0 + srow) * DMODEL + scol;

    float acc[4][4][4] = {};   // [mi][ni][frag]

    for (int k0 = 0; k0 < DMODEL; k0 += 16) {
        float4 xa = *(const float4*)(Xp + k0);
        float4 xb = *(const float4*)(Xp + k0 + 4);
        float4 wa = *(const float4*)(Wp + k0);
        float4 wb = *(const float4*)(Wp + k0 + 4);
        __syncthreads();   // previous iteration's frag reads done
        // round to tf32 (RN) while staging
        As[srow][scol + 0] = tf32_rn(xa.x); As[srow][scol + 1] = tf32_rn(xa.y);
        As[srow][scol + 2] = tf32_rn(xa.z); As[srow][scol + 3] = tf32_rn(xa.w);
        As[srow][scol + 4] = tf32_rn(xb.x); As[srow][scol + 5] = tf32_rn(xb.y);
        As[srow][scol + 6] = tf32_rn(xb.z); As[srow][scol + 7] = tf32_rn(xb.w);
        Bs[srow][scol + 0] = tf32_rn(wa.x); Bs[srow][scol + 1] = tf32_rn(wa.y);
        Bs[srow][scol + 2] = tf32_rn(wa.z); Bs[srow][scol + 3] = tf32_rn(wa.w);
        Bs[srow][scol + 4] = tf32_rn(wb.x); Bs[srow][scol + 5] = tf32_rn(wb.y);
        Bs[srow][scol + 6] = tf32_rn(wb.z); Bs[srow][scol + 7] = tf32_rn(wb.w);
        __syncthreads();

        #pragma unroll
        for (int kk = 0; kk < 16; kk += 8) {
            float a[4][4], b[4][2];
            #pragma unroll
            for (int mi = 0; mi < 4; mi++) {
                const int mr = wm + mi * 16;
                a[mi][0] = As[mr + g    ][kk + t];
                a[mi][1] = As[mr + g + 8][kk + t];
                a[mi][2] = As[mr + g    ][kk + t + 4];
                a[mi][3] = As[mr + g + 8][kk + t + 4];
            }
            #pragma unroll
            for (int ni = 0; ni < 4; ni++) {
                const int nr = wn + ni * 8 + g;
                b[ni][0] = Bs[nr][kk + t];
                b[ni][1] = Bs[nr][kk + t + 4];
            }
            #pragma unroll
            for (int mi = 0; mi < 4; mi++)
                #pragma unroll
                for (int ni = 0; ni < 4; ni++)
                    mma16n8k8(acc[mi][ni], a[mi], b[ni]);
        }
    }

    // Epilogue: c0,c1 -> (row g, cols 2t,2t+1); c2,c3 -> (row g+8, same cols)
    #pragma unroll
    for (int mi = 0; mi < 4; mi++) {
        #pragma unroll
        for (int ni = 0; ni < 4; ni++) {
            const int n = n0 + wn + ni * 8 + 2 * t;
            const float bx = bias[n], by = bias[n + 1];
            #pragma unroll
            for (int half = 0; half < 2; half++) {
                const int m = m0 + wm + mi * 16 + g + half * 8;
                float2 o;
                o.x = acc[mi][ni][half * 2 + 0] + bx;
                o.y = acc[mi][ni][half * 2 + 1] + by;
                if (mode == 0) {
                    const int bb = m >> 11;
                    const int s  = m & 2047;
                    const int h  = n >> 6;
                    size_t idx = (((size_t)(bb * NH + h) * S_LEN + s) * DK) + (size_t)(n & 63);
                    *(float2*)&Y[idx] = o;
                } else {
                    *(float2*)&Y[(size_t)m * DMODEL + n] = o;
                }
            }
        }
    }
}

// ---------------------------------------------------------------------------
// Flash attention (fp32 SIMT, as in the passing R1 kernel)
// ---------------------------------------------------------------------------
__global__ __launch_bounds__(256) void attn_kernel(float* __restrict__ AO)
{
    __shared__ __align__(16) float Qt[64][64];   // [d][i]
    __shared__ __align__(16) float KP[64][64];   // Kt[d][j] then P[i][j]
    __shared__ __align__(16) float Vs[64][64];   // [j][e]

    const int tid = threadIdx.x;
    const int tx = tid & 15;
    const int ty = tid >> 4;
    const int q0 = blockIdx.x * 64;
    const int bh = blockIdx.y;

    const float* Qg = g_Q + (size_t)bh * S_LEN * DK;
    const float* Kg = g_K + (size_t)bh * S_LEN * DK;
    const float* Vg = g_V + (size_t)bh * S_LEN * DK;

    const int lr = tid >> 2;
    const int lc = (tid & 3) * 16;

    {
        const float* p = Qg + (size_t)(q0 + lr) * DK + lc;
        #pragma unroll
        for (int i = 0; i < 4; i++) {
            float4 v = *(const float4*)(p + i * 4);
            Qt[lc + i * 4 + 0][lr] = v.x;
            Qt[lc + i * 4 + 1][lr] = v.y;
            Qt[lc + i * 4 + 2][lr] = v.z;
            Qt[lc + i * 4 + 3][lr] = v.w;
        }
    }

    float acc[4][4] = {};
    float mrow[4], lrow[4];
    #pragma unroll
    for (int i = 0; i < 4; i++) { mrow[i] = -1e30f; lrow[i] = 0.f; }

    for (int j0 = 0; j0 < S_LEN; j0 += 64) {
        const float* kp = Kg + (size_t)(j0 + lr) * DK + lc;
        const float* vp = Vg + (size_t)(j0 + lr) * DK + lc;
        float4 kv[4], vv[4];
        #pragma unroll
        for (int i = 0; i < 4; i++) {
            kv[i] = *(const float4*)(kp + i * 4);
            vv[i] = *(const float4*)(vp + i * 4);
        }
        __syncthreads();
        #pragma unroll
        for (int i = 0; i < 4; i++) {
            KP[lc + i * 4 + 0][lr] = kv[i].x;
            KP[lc + i * 4 + 1][lr] = kv[i].y;
            KP[lc + i * 4 + 2][lr] = kv[i].z;
            KP[lc + i * 4 + 3][lr] = kv[i].w;
            *(float4*)&Vs[lr][lc + i * 4] = vv[i];
        }
        __syncthreads();

        float s[4][4] = {};
        #pragma unroll
        for (int d = 0; d < 64; d++) {
            float4 ra = *(const float4*)&Qt[d][ty * 4];
            float4 rb = *(const float4*)&KP[d][tx * 4];
            float av[4] = {ra.x, ra.y, ra.z, ra.w};
            float bv[4] = {rb.x, rb.y, rb.z, rb.w};
            #pragma unroll
            for (int i = 0; i < 4; i++)
                #pragma unroll
                for (int j = 0; j < 4; j++)
                    s[i][j] = fmaf(av[i], bv[j], s[i][j]);
        }

        #pragma unroll
        for (int i = 0; i < 4; i++) {
            #pragma unroll
            for (int j = 0; j < 4; j++) s[i][j] *= 0.125f;
            float mx = fmaxf(fmaxf(s[i][0], s[i][1]), fmaxf(s[i][2], s[i][3]));
            mx = fmaxf(mx, __shfl_xor_sync(0xffffffffu, mx, 1));
            mx = fmaxf(mx, __shfl_xor_sync(0xffffffffu, mx, 2));
            mx = fmaxf(mx, __shfl_xor_sync(0xffffffffu, mx, 4));
            mx = fmaxf(mx, __shfl_xor_sync(0xffffffffu, mx, 8));
            float mnew = fmaxf(mrow[i], mx);
            float alpha = __expf(mrow[i] - mnew);
            mrow[i] = mnew;
            float rs = 0.f;
            #pragma unroll
            for (int j = 0; j < 4; j++) {
                s[i][j] = __expf(s[i][j] - mnew);
                rs += s[i][j];
            }
            rs += __shfl_xor_sync(0xffffffffu, rs, 1);
            rs += __shfl_xor_sync(0xffffffffu, rs, 2);
            rs += __shfl_xor_sync(0xffffffffu, rs, 4);
            rs += __shfl_xor_sync(0xffffffffu, rs, 8);
            lrow[i] = lrow[i] * alpha + rs;
            #pragma unroll
            for (int j = 0; j < 4; j++) acc[i][j] *= alpha;
        }

        __syncthreads();
        #pragma unroll
        for (int i = 0; i < 4; i++)
            *(float4*)&KP[ty * 4 + i][tx * 4] =
                make_float4(s[i][0], s[i][1], s[i][2], s[i][3]);
        __syncthreads();

        #pragma unroll
        for (int j = 0; j < 64; j++) {
            float4 rv = *(const float4*)&Vs[j][tx * 4];
            float bv[4] = {rv.x, rv.y, rv.z, rv.w};
            float pv[4];
            #pragma unroll
            for (int i = 0; i < 4; i++) pv[i] = KP[ty * 4 + i][j];
            #pragma unroll
            for (int i = 0; i < 4; i++)
                #pragma unroll
                for (int e = 0; e < 4; e++)
                    acc[i][e] = fmaf(pv[i], bv[e], acc[i][e]);
        }
    }

    const int h = bh & (NH - 1);
    const int b = bh >> 4;
    #pragma unroll
    for (int i = 0; i < 4; i++) {
        const int srow = q0 + ty * 4 + i;
        const float inv = 1.0f / lrow[i];
        float4 r = make_float4(acc[i][0] * inv, acc[i][1] * inv,
                               acc[i][2] * inv, acc[i][3] * inv);
        size_t idx = ((size_t)(b * S_LEN + srow) * DMODEL) + (size_t)(h * DK + tx * 4);
        *(float4*)&AO[idx] = r;
    }
}

// ---------------------------------------------------------------------------
extern "C" void kernel_launch(void* const* d_in, const int* in_sizes, int n_in,
                              void* d_out, int out_size)
{
    (void)in_sizes; (void)n_in; (void)out_size;
    const float* q  = (const float*)d_in[0];
    const float* k  = (const float*)d_in[1];
    const float* v  = (const float*)d_in[2];
    const float* Wq = (const float*)d_in[3];
    const float* bq = (const float*)d_in[4];
    const float* Wk = (const float*)d_in[5];
    const float* bk = (const float*)d_in[6];
    const float* Wv = (const float*)d_in[7];
    const float* bv = (const float*)d_in[8];
    const float* Wo = (const float*)d_in[9];
    const float* bo = (const float*)d_in[10];
    float* out = (float*)d_out;

    float *Qp, *Kp, *Vp, *AOp;
    cudaGetSymbolAddress((void**)&Qp,  g_Q);
    cudaGetSymbolAddress((void**)&Kp,  g_K);
    cudaGetSymbolAddress((void**)&Vp,  g_V);
    cudaGetSymbolAddress((void**)&AOp, g_AO);

    dim3 ggrid(DMODEL / 128, M_TOT / 128);   // (8, 64)
    gemm_mma_kernel<<<ggrid, 256>>>(q, Wq, bq, Qp, 0);
    gemm_mma_kernel<<<ggrid, 256>>>(k, Wk, bk, Kp, 0);
    gemm_mma_kernel<<<ggrid, 256>>>(v, Wv, bv, Vp, 0);

    attn_kernel<<<dim3(S_LEN / 64, BATCH * NH), 256>>>(AOp);

    gemm_mma_kernel<<<ggrid, 256>>>(AOp, Wo, bo, out, 1);
}

// round 6
// speedup vs baseline: 1.6182x; 1.1440x over previous
#include <cuda_runtime.h>
#include <cstdint>
#include <math.h>

#define S_LEN  2048
#define DMODEL 1024
#define NH     16
#define DK     64
#define BATCH  4
#define M_TOT  (BATCH * S_LEN)   // 8192

// Scratch (static __device__ — no allocations allowed)
__device__ float g_Q[BATCH * NH * S_LEN * DK];   // [b,h,s,d] (tf32-rounded)
__device__ float g_K[BATCH * NH * S_LEN * DK];
__device__ float g_V[BATCH * NH * S_LEN * DK];
__device__ float g_AO[(size_t)M_TOT * DMODEL];   // attention out, [m][e] row-major

// ---------------------------------------------------------------------------
__device__ __forceinline__ float tf32_rn(float x) {
    uint32_t u;
    asm("cvt.rna.tf32.f32 %0, %1;" : "=r"(u) : "f"(x));
    return __uint_as_float(u);
}

// m16n8k8 tf32 mma: D += A*B. A row-major 16x8, B[k][n] (col), C/D fp32.
__device__ __forceinline__ void mma16n8k8(float* d, const float* a, const float* b) {
    asm volatile(
        "mma.sync.aligned.m16n8k8.row.col.f32.tf32.tf32.f32 "
        "{%0,%1,%2,%3}, {%4,%5,%6,%7}, {%8,%9}, {%0,%1,%2,%3};"
        : "+f"(d[0]), "+f"(d[1]), "+f"(d[2]), "+f"(d[3])
        : "r"(__float_as_uint(a[0])), "r"(__float_as_uint(a[1])),
          "r"(__float_as_uint(a[2])), "r"(__float_as_uint(a[3])),
          "r"(__float_as_uint(b[0])), "r"(__float_as_uint(b[1])));
}

// ---------------------------------------------------------------------------
// Tensor-core GEMM: Y = X @ W^T + bias.  CTA 128x128, 8 warps (2m x 4n), BK=16.
// mode 0: scatter into [b,h,s,d] head layout, tf32-RN-rounded (feeds attn mma)
// mode 1: plain [m][n] row-major fp32
// ---------------------------------------------------------------------------
__global__ __launch_bounds__(256, 2) void gemm_mma_kernel(
    const float* __restrict__ X, const float* __restrict__ W,
    const float* __restrict__ bias, float* __restrict__ Y, int mode)
{
    __shared__ __align__(16) float As[128][20];
    __shared__ __align__(16) float Bs[128][20];

    const int tid  = threadIdx.x;
    const int lane = tid & 31;
    const int wid  = tid >> 5;
    const int g = lane >> 2;
    const int t = lane & 3;
    const int wm = (wid >> 2) * 64;
    const int wn = (wid & 3) * 32;
    const int m0 = blockIdx.y * 128;
    const int n0 = blockIdx.x * 128;

    const int srow = tid >> 1;
    const int scol = (tid & 1) * 8;
    const float* Xp = X + (size_t)(m0 + srow) * DMODEL + scol;
    const float* Wp = W + (size_t)(n0 + srow) * DMODEL + scol;

    float acc[4][4][4] = {};

    for (int k0 = 0; k0 < DMODEL; k0 += 16) {
        float4 xa = *(const float4*)(Xp + k0);
        float4 xb = *(const float4*)(Xp + k0 + 4);
        float4 wa = *(const float4*)(Wp + k0);
        float4 wb = *(const float4*)(Wp + k0 + 4);
        __syncthreads();
        As[srow][scol + 0] = tf32_rn(xa.x); As[srow][scol + 1] = tf32_rn(xa.y);
        As[srow][scol + 2] = tf32_rn(xa.z); As[srow][scol + 3] = tf32_rn(xa.w);
        As[srow][scol + 4] = tf32_rn(xb.x); As[srow][scol + 5] = tf32_rn(xb.y);
        As[srow][scol + 6] = tf32_rn(xb.z); As[srow][scol + 7] = tf32_rn(xb.w);
        Bs[srow][scol + 0] = tf32_rn(wa.x); Bs[srow][scol + 1] = tf32_rn(wa.y);
        Bs[srow][scol + 2] = tf32_rn(wa.z); Bs[srow][scol + 3] = tf32_rn(wa.w);
        Bs[srow][scol + 4] = tf32_rn(wb.x); Bs[srow][scol + 5] = tf32_rn(wb.y);
        Bs[srow][scol + 6] = tf32_rn(wb.z); Bs[srow][scol + 7] = tf32_rn(wb.w);
        __syncthreads();

        #pragma unroll
        for (int kk = 0; kk < 16; kk += 8) {
            float a[4][4], b[4][2];
            #pragma unroll
            for (int mi = 0; mi < 4; mi++) {
                const int mr = wm + mi * 16;
                a[mi][0] = As[mr + g    ][kk + t];
                a[mi][1] = As[mr + g + 8][kk + t];
                a[mi][2] = As[mr + g    ][kk + t + 4];
                a[mi][3] = As[mr + g + 8][kk + t + 4];
            }
            #pragma unroll
            for (int ni = 0; ni < 4; ni++) {
                const int nr = wn + ni * 8 + g;
                b[ni][0] = Bs[nr][kk + t];
                b[ni][1] = Bs[nr][kk + t + 4];
            }
            #pragma unroll
            for (int mi = 0; mi < 4; mi++)
                #pragma unroll
                for (int ni = 0; ni < 4; ni++)
                    mma16n8k8(acc[mi][ni], a[mi], b[ni]);
        }
    }

    #pragma unroll
    for (int mi = 0; mi < 4; mi++) {
        #pragma unroll
        for (int ni = 0; ni < 4; ni++) {
            const int n = n0 + wn + ni * 8 + 2 * t;
            const float bx = bias[n], by = bias[n + 1];
            #pragma unroll
            for (int half = 0; half < 2; half++) {
                const int m = m0 + wm + mi * 16 + g + half * 8;
                float2 o;
                o.x = acc[mi][ni][half * 2 + 0] + bx;
                o.y = acc[mi][ni][half * 2 + 1] + by;
                if (mode == 0) {
                    o.x = tf32_rn(o.x);      // Q/K/V feed tf32 mma in attention
                    o.y = tf32_rn(o.y);
                    const int bb = m >> 11;
                    const int s  = m & 2047;
                    const int h  = n >> 6;
                    size_t idx = (((size_t)(bb * NH + h) * S_LEN + s) * DK) + (size_t)(n & 63);
                    *(float2*)&Y[idx] = o;
                } else {
                    *(float2*)&Y[(size_t)m * DMODEL + n] = o;
                }
            }
        }
    }
}

// ---------------------------------------------------------------------------
// Tensor-core flash attention. CTA = one (b,h), 128 q-rows; kv-tiles of 64.
// 8 warps x 16 q-rows. Scores and PV on mma.sync tf32; online softmax in regs.
// smem: Qs[128][68] + KP[128][68] (K rows 0..63 / P rows 0..127 union) + Vs[64][68]
// ---------------------------------------------------------------------------
#define ATT_SMEM ((128*68 + 128*68 + 64*68) * 4)   // 87040 B

__global__ __launch_bounds__(256, 2) void attn_mma_kernel(float* __restrict__ AO)
{
    extern __shared__ __align__(16) float sm[];
    float (*Qs)[68] = (float(*)[68])sm;               // 128 rows
    float (*KP)[68] = (float(*)[68])(sm + 128 * 68);  // 128 rows
    float (*Vs)[68] = (float(*)[68])(sm + 256 * 68);  // 64 rows

    const int tid  = threadIdx.x;
    const int lane = tid & 31;
    const int wid  = tid >> 5;
    const int g = lane >> 2;
    const int t = lane & 3;
    const int q0 = blockIdx.x * 128;
    const int bh = blockIdx.y;
    const int mr = wid * 16;

    const float* Qg = g_Q + (size_t)bh * S_LEN * DK;
    const float* Kg = g_K + (size_t)bh * S_LEN * DK;
    const float* Vg = g_V + (size_t)bh * S_LEN * DK;

    // load Q tile (128 x 64)
    {
        const int r = tid >> 1, cb = (tid & 1) * 32;
        const float* p = Qg + (size_t)(q0 + r) * DK + cb;
        #pragma unroll
        for (int i = 0; i < 8; i++)
            *(float4*)&Qs[r][cb + i * 4] = *(const float4*)(p + i * 4);
    }

    float oacc[8][4] = {};
    float mrow[2] = {-1e30f, -1e30f};
    float lrow[2] = {0.f, 0.f};

    for (int j0 = 0; j0 < S_LEN; j0 += 64) {
        __syncthreads();   // prev PV reads of KP/Vs done (and Q stores on iter 0)
        {
            const int r = tid >> 2, cb = (tid & 3) * 16;
            const float* kp = Kg + (size_t)(j0 + r) * DK + cb;
            const float* vp = Vg + (size_t)(j0 + r) * DK + cb;
            #pragma unroll
            for (int i = 0; i < 4; i++) {
                *(float4*)&KP[r][cb + i * 4] = *(const float4*)(kp + i * 4);
                *(float4*)&Vs[r][cb + i * 4] = *(const float4*)(vp + i * 4);
            }
        }
        __syncthreads();

        // scores: S = Q K^T  (warp: 16 rows x 64 keys)
        float sacc[8][4] = {};
        #pragma unroll
        for (int kk = 0; kk < 64; kk += 8) {
            float a[4];
            a[0] = Qs[mr + g    ][kk + t];
            a[1] = Qs[mr + g + 8][kk + t];
            a[2] = Qs[mr + g    ][kk + t + 4];
            a[3] = Qs[mr + g + 8][kk + t + 4];
            #pragma unroll
            for (int ni = 0; ni < 8; ni++) {
                float b[2];
                b[0] = KP[ni * 8 + g][kk + t];
                b[1] = KP[ni * 8 + g][kk + t + 4];
                mma16n8k8(sacc[ni], a, b);
            }
        }

        // online softmax (rows g / g+8; row lives in a lane quad -> 2 shfls)
        #pragma unroll
        for (int half = 0; half < 2; half++) {
            float mx = -1e30f;
            #pragma unroll
            for (int ni = 0; ni < 8; ni++) {
                sacc[ni][half * 2 + 0] *= 0.125f;
                sacc[ni][half * 2 + 1] *= 0.125f;
                mx = fmaxf(mx, fmaxf(sacc[ni][half * 2], sacc[ni][half * 2 + 1]));
            }
            mx = fmaxf(mx, __shfl_xor_sync(0xffffffffu, mx, 1));
            mx = fmaxf(mx, __shfl_xor_sync(0xffffffffu, mx, 2));
            const float mnew = fmaxf(mrow[half], mx);
            const float alpha = __expf(mrow[half] - mnew);
            mrow[half] = mnew;
            float sum = 0.f;
            #pragma unroll
            for (int ni = 0; ni < 8; ni++) {
                float p0 = __expf(sacc[ni][half * 2 + 0] - mnew);
                float p1 = __expf(sacc[ni][half * 2 + 1] - mnew);
                sacc[ni][half * 2 + 0] = p0;
                sacc[ni][half * 2 + 1] = p1;
                sum += p0 + p1;
            }
            sum += __shfl_xor_sync(0xffffffffu, sum, 1);
            sum += __shfl_xor_sync(0xffffffffu, sum, 2);
            lrow[half] = lrow[half] * alpha + sum;
            #pragma unroll
            for (int ni = 0; ni < 8; ni++) {
                oacc[ni][half * 2 + 0] *= alpha;
                oacc[ni][half * 2 + 1] *= alpha;
            }
        }

        __syncthreads();   // all warps' score mmas finished reading K from KP
        // store P (tf32 RN) over KP rows 0..127
        #pragma unroll
        for (int ni = 0; ni < 8; ni++) {
            const int c = ni * 8 + 2 * t;
            *(float2*)&KP[mr + g    ][c] = make_float2(tf32_rn(sacc[ni][0]), tf32_rn(sacc[ni][1]));
            *(float2*)&KP[mr + g + 8][c] = make_float2(tf32_rn(sacc[ni][2]), tf32_rn(sacc[ni][3]));
        }
        __syncthreads();

        // O += P @ V   (B-frag = V^T read from row-major Vs)
        #pragma unroll
        for (int kk = 0; kk < 64; kk += 8) {
            float a[4];
            a[0] = KP[mr + g    ][kk + t];
            a[1] = KP[mr + g + 8][kk + t];
            a[2] = KP[mr + g    ][kk + t + 4];
            a[3] = KP[mr + g + 8][kk + t + 4];
            #pragma unroll
            for (int ni = 0; ni < 8; ni++) {
                float b[2];
                b[0] = Vs[kk + t    ][ni * 8 + g];
                b[1] = Vs[kk + t + 4][ni * 8 + g];
                mma16n8k8(oacc[ni], a, b);
            }
        }
    }

    // epilogue: AO[b*S + s][h*64 + d] = O / l
    const int h = bh & (NH - 1);
    const int b = bh >> 4;
    const float inv0 = 1.0f / lrow[0];
    const float inv1 = 1.0f / lrow[1];
    #pragma unroll
    for (int ni = 0; ni < 8; ni++) {
        const int d = ni * 8 + 2 * t;
        size_t i0 = ((size_t)(b * S_LEN + q0 + mr + g    )) * DMODEL + (size_t)(h * DK + d);
        size_t i1 = ((size_t)(b * S_LEN + q0 + mr + g + 8)) * DMODEL + (size_t)(h * DK + d);
        *(float2*)&AO[i0] = make_float2(oacc[ni][0] * inv0, oacc[ni][1] * inv0);
        *(float2*)&AO[i1] = make_float2(oacc[ni][2] * inv1, oacc[ni][3] * inv1);
    }
}

// ---------------------------------------------------------------------------
extern "C" void kernel_launch(void* const* d_in, const int* in_sizes, int n_in,
                              void* d_out, int out_size)
{
    (void)in_sizes; (void)n_in; (void)out_size;
    const float* q  = (const float*)d_in[0];
    const float* k  = (const float*)d_in[1];
    const float* v  = (const float*)d_in[2];
    const float* Wq = (const float*)d_in[3];
    const float* bq = (const float*)d_in[4];
    const float* Wk = (const float*)d_in[5];
    const float* bk = (const float*)d_in[6];
    const float* Wv = (const float*)d_in[7];
    const float* bv = (const float*)d_in[8];
    const float* Wo = (const float*)d_in[9];
    const float* bo = (const float*)d_in[10];
    float* out = (float*)d_out;

    float *Qp, *Kp, *Vp, *AOp;
    cudaGetSymbolAddress((void**)&Qp,  g_Q);
    cudaGetSymbolAddress((void**)&Kp,  g_K);
    cudaGetSymbolAddress((void**)&Vp,  g_V);
    cudaGetSymbolAddress((void**)&AOp, g_AO);

    cudaFuncSetAttribute(attn_mma_kernel,
                         cudaFuncAttributeMaxDynamicSharedMemorySize, ATT_SMEM);

    dim3 ggrid(DMODEL / 128, M_TOT / 128);   // (8, 64)
    gemm_mma_kernel<<<ggrid, 256>>>(q, Wq, bq, Qp, 0);
    gemm_mma_kernel<<<ggrid, 256>>>(k, Wk, bk, Kp, 0);
    gemm_mma_kernel<<<ggrid, 256>>>(v, Wv, bv, Vp, 0);

    attn_mma_kernel<<<dim3(S_LEN / 128, BATCH * NH), 256, ATT_SMEM>>>(AOp);

    gemm_mma_kernel<<<ggrid, 256>>>(AOp, Wo, bo, out, 1);
}

// round 7
// speedup vs baseline: 2.4580x; 1.5190x over previous
#include <cuda_runtime.h>
#include <cstdint>
#include <math.h>

#define S_LEN  2048
#define DMODEL 1024
#define NH     16
#define DK     64
#define BATCH  4
#define M_TOT  (BATCH * S_LEN)   // 8192

// Scratch (static __device__ — no allocations allowed)
__device__ float g_Q[BATCH * NH * S_LEN * DK];   // [b,h,s,d] (tf32-rounded)
__device__ float g_K[BATCH * NH * S_LEN * DK];
__device__ float g_V[BATCH * NH * S_LEN * DK];
__device__ float g_AO[(size_t)M_TOT * DMODEL];   // attention out, [m][e] row-major

// ---------------------------------------------------------------------------
__device__ __forceinline__ float tf32_rn(float x) {
    uint32_t u;
    asm("cvt.rna.tf32.f32 %0, %1;" : "=r"(u) : "f"(x));
    return __uint_as_float(u);
}

// m16n8k8 tf32 mma: D += A*B. A row-major 16x8, B[k][n] (col), C/D fp32.
__device__ __forceinline__ void mma16n8k8(float* d, const float* a, const float* b) {
    asm volatile(
        "mma.sync.aligned.m16n8k8.row.col.f32.tf32.tf32.f32 "
        "{%0,%1,%2,%3}, {%4,%5,%6,%7}, {%8,%9}, {%0,%1,%2,%3};"
        : "+f"(d[0]), "+f"(d[1]), "+f"(d[2]), "+f"(d[3])
        : "r"(__float_as_uint(a[0])), "r"(__float_as_uint(a[1])),
          "r"(__float_as_uint(a[2])), "r"(__float_as_uint(a[3])),
          "r"(__float_as_uint(b[0])), "r"(__float_as_uint(b[1])));
}

// ---------------------------------------------------------------------------
// Tensor-core GEMM: Y = X @ W^T + bias.  CTA 128x128, 8 warps (2m x 4n), BK=16.
// mode 0: scatter into [b,h,s,d] head layout, tf32-RN-rounded (feeds attn mma)
// mode 1: plain [m][n] row-major fp32
// ---------------------------------------------------------------------------
__global__ __launch_bounds__(256, 2) void gemm_mma_kernel(
    const float* __restrict__ X, const float* __restrict__ W,
    const float* __restrict__ bias, float* __restrict__ Y, int mode)
{
    __shared__ __align__(16) float As[128][20];
    __shared__ __align__(16) float Bs[128][20];

    const int tid  = threadIdx.x;
    const int lane = tid & 31;
    const int wid  = tid >> 5;
    const int g = lane >> 2;
    const int t = lane & 3;
    const int wm = (wid >> 2) * 64;
    const int wn = (wid & 3) * 32;
    const int m0 = blockIdx.y * 128;
    const int n0 = blockIdx.x * 128;

    const int srow = tid >> 1;
    const int scol = (tid & 1) * 8;
    const float* Xp = X + (size_t)(m0 + srow) * DMODEL + scol;
    const float* Wp = W + (size_t)(n0 + srow) * DMODEL + scol;

    float acc[4][4][4] = {};

    for (int k0 = 0; k0 < DMODEL; k0 += 16) {
        float4 xa = *(const float4*)(Xp + k0);
        float4 xb = *(const float4*)(Xp + k0 + 4);
        float4 wa = *(const float4*)(Wp + k0);
        float4 wb = *(const float4*)(Wp + k0 + 4);
        __syncthreads();
        As[srow][scol + 0] = tf32_rn(xa.x); As[srow][scol + 1] = tf32_rn(xa.y);
        As[srow][scol + 2] = tf32_rn(xa.z); As[srow][scol + 3] = tf32_rn(xa.w);
        As[srow][scol + 4] = tf32_rn(xb.x); As[srow][scol + 5] = tf32_rn(xb.y);
        As[srow][scol + 6] = tf32_rn(xb.z); As[srow][scol + 7] = tf32_rn(xb.w);
        Bs[srow][scol + 0] = tf32_rn(wa.x); Bs[srow][scol + 1] = tf32_rn(wa.y);
        Bs[srow][scol + 2] = tf32_rn(wa.z); Bs[srow][scol + 3] = tf32_rn(wa.w);
        Bs[srow][scol + 4] = tf32_rn(wb.x); Bs[srow][scol + 5] = tf32_rn(wb.y);
        Bs[srow][scol + 6] = tf32_rn(wb.z); Bs[srow][scol + 7] = tf32_rn(wb.w);
        __syncthreads();

        #pragma unroll
        for (int kk = 0; kk < 16; kk += 8) {
            float a[4][4], b[4][2];
            #pragma unroll
            for (int mi = 0; mi < 4; mi++) {
                const int mr = wm + mi * 16;
                a[mi][0] = As[mr + g    ][kk + t];
                a[mi][1] = As[mr + g + 8][kk + t];
                a[mi][2] = As[mr + g    ][kk + t + 4];
                a[mi][3] = As[mr + g + 8][kk + t + 4];
            }
            #pragma unroll
            for (int ni = 0; ni < 4; ni++) {
                const int nr = wn + ni * 8 + g;
                b[ni][0] = Bs[nr][kk + t];
                b[ni][1] = Bs[nr][kk + t + 4];
            }
            #pragma unroll
            for (int mi = 0; mi < 4; mi++)
                #pragma unroll
                for (int ni = 0; ni < 4; ni++)
                    mma16n8k8(acc[mi][ni], a[mi], b[ni]);
        }
    }

    #pragma unroll
    for (int mi = 0; mi < 4; mi++) {
        #pragma unroll
        for (int ni = 0; ni < 4; ni++) {
            const int n = n0 + wn + ni * 8 + 2 * t;
            const float bx = bias[n], by = bias[n + 1];
            #pragma unroll
            for (int half = 0; half < 2; half++) {
                const int m = m0 + wm + mi * 16 + g + half * 8;
                float2 o;
                o.x = acc[mi][ni][half * 2 + 0] + bx;
                o.y = acc[mi][ni][half * 2 + 1] + by;
                if (mode == 0) {
                    o.x = tf32_rn(o.x);      // Q/K/V feed tf32 mma in attention
                    o.y = tf32_rn(o.y);
                    const int bb = m >> 11;
                    const int s  = m & 2047;
                    const int h  = n >> 6;
                    size_t idx = (((size_t)(bb * NH + h) * S_LEN + s) * DK) + (size_t)(n & 63);
                    *(float2*)&Y[idx] = o;
                } else {
                    *(float2*)&Y[(size_t)m * DMODEL + n] = o;
                }
            }
        }
    }
}

// ---------------------------------------------------------------------------
// Tensor-core flash attention v2.
// CTA = one (b,h) x 128 q-rows; 4 warps x 32 q-rows (mi=2); kv-tiles of 64.
// Q fragments hoisted to registers (loaded once); smem Q region aliased with
// the K/P union buffer. Vs stride 72 -> conflict-free PV B-frag loads.
// smem: QK[128][68] (Q prologue -> K rows 0..63 / P rows 0..127) + Vs[64][72]
// ---------------------------------------------------------------------------
#define ATT_SMEM ((128 * 68 + 64 * 72) * 4)   // 53248 B

__global__ __launch_bounds__(128, 2) void attn_mma_kernel(float* __restrict__ AO)
{
    extern __shared__ __align__(16) float sm[];
    float (*QK)[68] = (float(*)[68])sm;              // 128 rows
    float (*Vs)[72] = (float(*)[72])(sm + 128 * 68); // 64 rows

    const int tid  = threadIdx.x;
    const int lane = tid & 31;
    const int wid  = tid >> 5;          // 0..3
    const int g = lane >> 2;
    const int t = lane & 3;
    const int q0 = blockIdx.x * 128;
    const int bh = blockIdx.y;
    const int mr = wid * 32;

    const float* Qg = g_Q + (size_t)bh * S_LEN * DK;
    const float* Kg = g_K + (size_t)bh * S_LEN * DK;
    const float* Vg = g_V + (size_t)bh * S_LEN * DK;

    // prologue: stage Q tile (128 x 64), then hoist this warp's fragments
    {
        const float* p = Qg + (size_t)(q0 + tid) * DK;
        #pragma unroll
        for (int i = 0; i < 16; i++)
            *(float4*)&QK[tid][i * 4] = *(const float4*)(p + i * 4);
    }
    __syncthreads();

    float qf[2][8][4];
    #pragma unroll
    for (int mi = 0; mi < 2; mi++) {
        const int r0 = mr + mi * 16 + g;
        #pragma unroll
        for (int kk8 = 0; kk8 < 8; kk8++) {
            const int c = kk8 * 8 + t;
            qf[mi][kk8][0] = QK[r0    ][c];
            qf[mi][kk8][1] = QK[r0 + 8][c];
            qf[mi][kk8][2] = QK[r0    ][c + 4];
            qf[mi][kk8][3] = QK[r0 + 8][c + 4];
        }
    }

    float oacc[2][8][4] = {};
    float mrow[2][2], lrow[2][2];
    #pragma unroll
    for (int mi = 0; mi < 2; mi++)
        #pragma unroll
        for (int hf = 0; hf < 2; hf++) { mrow[mi][hf] = -1e30f; lrow[mi][hf] = 0.f; }

    for (int j0 = 0; j0 < S_LEN; j0 += 64) {
        __syncthreads();   // prev PV reads of P/Vs done (iter0: Q frag reads done)
        {
            const int r = tid >> 1, cb = (tid & 1) * 32;
            const float* kp = Kg + (size_t)(j0 + r) * DK + cb;
            const float* vp = Vg + (size_t)(j0 + r) * DK + cb;
            #pragma unroll
            for (int i = 0; i < 8; i++) {
                *(float4*)&QK[r][cb + i * 4] = *(const float4*)(kp + i * 4);
                *(float4*)&Vs[r][cb + i * 4] = *(const float4*)(vp + i * 4);
            }
        }
        __syncthreads();

        // scores: S = Q K^T  (warp: 32 rows x 64 keys; B frags reused across mi)
        float sacc[2][8][4] = {};
        #pragma unroll
        for (int kk8 = 0; kk8 < 8; kk8++) {
            const int kc = kk8 * 8 + t;
            float b[8][2];
            #pragma unroll
            for (int ni = 0; ni < 8; ni++) {
                b[ni][0] = QK[ni * 8 + g][kc];
                b[ni][1] = QK[ni * 8 + g][kc + 4];
            }
            #pragma unroll
            for (int ni = 0; ni < 8; ni++)
                #pragma unroll
                for (int mi = 0; mi < 2; mi++)
                    mma16n8k8(sacc[mi][ni], qf[mi][kk8], b[ni]);
        }

        // online softmax per row (row in lane quad -> 2 shfls)
        #pragma unroll
        for (int mi = 0; mi < 2; mi++) {
            #pragma unroll
            for (int hf = 0; hf < 2; hf++) {
                float mx = -1e30f;
                #pragma unroll
                for (int ni = 0; ni < 8; ni++) {
                    sacc[mi][ni][hf * 2 + 0] *= 0.125f;
                    sacc[mi][ni][hf * 2 + 1] *= 0.125f;
                    mx = fmaxf(mx, fmaxf(sacc[mi][ni][hf * 2], sacc[mi][ni][hf * 2 + 1]));
                }
                mx = fmaxf(mx, __shfl_xor_sync(0xffffffffu, mx, 1));
                mx = fmaxf(mx, __shfl_xor_sync(0xffffffffu, mx, 2));
                const float mnew = fmaxf(mrow[mi][hf], mx);
                const float alpha = __expf(mrow[mi][hf] - mnew);
                mrow[mi][hf] = mnew;
                float sum = 0.f;
                #pragma unroll
                for (int ni = 0; ni < 8; ni++) {
                    float p0 = __expf(sacc[mi][ni][hf * 2 + 0] - mnew);
                    float p1 = __expf(sacc[mi][ni][hf * 2 + 1] - mnew);
                    sacc[mi][ni][hf * 2 + 0] = p0;
                    sacc[mi][ni][hf * 2 + 1] = p1;
                    sum += p0 + p1;
                }
                sum += __shfl_xor_sync(0xffffffffu, sum, 1);
                sum += __shfl_xor_sync(0xffffffffu, sum, 2);
                lrow[mi][hf] = lrow[mi][hf] * alpha + sum;
                #pragma unroll
                for (int ni = 0; ni < 8; ni++) {
                    oacc[mi][ni][hf * 2 + 0] *= alpha;
                    oacc[mi][ni][hf * 2 + 1] *= alpha;
                }
            }
        }

        __syncthreads();   // all warps' score mmas finished reading K
        // store P (tf32 RN) over QK rows 0..127
        #pragma unroll
        for (int mi = 0; mi < 2; mi++) {
            const int r0 = mr + mi * 16 + g;
            #pragma unroll
            for (int ni = 0; ni < 8; ni++) {
                const int c = ni * 8 + 2 * t;
                *(float2*)&QK[r0    ][c] =
                    make_float2(tf32_rn(sacc[mi][ni][0]), tf32_rn(sacc[mi][ni][1]));
                *(float2*)&QK[r0 + 8][c] =
                    make_float2(tf32_rn(sacc[mi][ni][2]), tf32_rn(sacc[mi][ni][3]));
            }
        }
        __syncthreads();

        // O += P @ V   (B-frag = V^T from row-major Vs, stride 72: conflict-free)
        #pragma unroll
        for (int kk8 = 0; kk8 < 8; kk8++) {
            const int kc = kk8 * 8 + t;
            float a[2][4], b[8][2];
            #pragma unroll
            for (int mi = 0; mi < 2; mi++) {
                const int r0 = mr + mi * 16 + g;
                a[mi][0] = QK[r0    ][kc];
                a[mi][1] = QK[r0 + 8][kc];
                a[mi][2] = QK[r0    ][kc + 4];
                a[mi][3] = QK[r0 + 8][kc + 4];
            }
            #pragma unroll
            for (int ni = 0; ni < 8; ni++) {
                b[ni][0] = Vs[kc    ][ni * 8 + g];
                b[ni][1] = Vs[kc + 4][ni * 8 + g];
            }
            #pragma unroll
            for (int ni = 0; ni < 8; ni++)
                #pragma unroll
                for (int mi = 0; mi < 2; mi++)
                    mma16n8k8(oacc[mi][ni], a[mi], b[ni]);
        }
    }

    // epilogue: AO[b*S + s][h*64 + d] = O / l
    const int h = bh & (NH - 1);
    const int b = bh >> 4;
    #pragma unroll
    for (int mi = 0; mi < 2; mi++) {
        const float inv0 = 1.0f / lrow[mi][0];
        const float inv1 = 1.0f / lrow[mi][1];
        const int r0 = q0 + mr + mi * 16 + g;
        #pragma unroll
        for (int ni = 0; ni < 8; ni++) {
            const int d = ni * 8 + 2 * t;
            size_t i0 = ((size_t)(b * S_LEN + r0    )) * DMODEL + (size_t)(h * DK + d);
            size_t i1 = ((size_t)(b * S_LEN + r0 + 8)) * DMODEL + (size_t)(h * DK + d);
            *(float2*)&AO[i0] = make_float2(oacc[mi][ni][0] * inv0, oacc[mi][ni][1] * inv0);
            *(float2*)&AO[i1] = make_float2(oacc[mi][ni][2] * inv1, oacc[mi][ni][3] * inv1);
        }
    }
}

// ---------------------------------------------------------------------------
extern "C" void kernel_launch(void* const* d_in, const int* in_sizes, int n_in,
                              void* d_out, int out_size)
{
    (void)in_sizes; (void)n_in; (void)out_size;
    const float* q  = (const float*)d_in[0];
    const float* k  = (const float*)d_in[1];
    const float* v  = (const float*)d_in[2];
    const float* Wq = (const float*)d_in[3];
    const float* bq = (const float*)d_in[4];
    const float* Wk = (const float*)d_in[5];
    const float* bk = (const float*)d_in[6];
    const float* Wv = (const float*)d_in[7];
    const float* bv = (const float*)d_in[8];
    const float* Wo = (const float*)d_in[9];
    const float* bo = (const float*)d_in[10];
    float* out = (float*)d_out;

    float *Qp, *Kp, *Vp, *AOp;
    cudaGetSymbolAddress((void**)&Qp,  g_Q);
    cudaGetSymbolAddress((void**)&Kp,  g_K);
    cudaGetSymbolAddress((void**)&Vp,  g_V);
    cudaGetSymbolAddress((void**)&AOp, g_AO);

    cudaFuncSetAttribute(attn_mma_kernel,
                         cudaFuncAttributeMaxDynamicSharedMemorySize, ATT_SMEM);

    dim3 ggrid(DMODEL / 128, M_TOT / 128);   // (8, 64)
    gemm_mma_kernel<<<ggrid, 256>>>(q, Wq, bq, Qp, 0);
    gemm_mma_kernel<<<ggrid, 256>>>(k, Wk, bk, Kp, 0);
    gemm_mma_kernel<<<ggrid, 256>>>(v, Wv, bv, Vp, 0);

    attn_mma_kernel<<<dim3(S_LEN / 128, BATCH * NH), 128, ATT_SMEM>>>(AOp);

    gemm_mma_kernel<<<ggrid, 256>>>(AOp, Wo, bo, out, 1);
}

// round 9
// speedup vs baseline: 2.8442x; 1.1571x over previous
#include <cuda_runtime.h>
#include <cstdint>
#include <math.h>

#define S_LEN  2048
#define DMODEL 1024
#define NH     16
#define DK     64
#define BATCH  4
#define M_TOT  (BATCH * S_LEN)   // 8192

// Scratch (static __device__ — no allocations allowed)
__device__ float g_Q[BATCH * NH * S_LEN * DK];   // [b,h,s,d] (tf32-rounded)
__device__ float g_K[BATCH * NH * S_LEN * DK];
__device__ float g_V[BATCH * NH * S_LEN * DK];
__device__ float g_AO[(size_t)M_TOT * DMODEL];   // attention out, [m][e] row-major

// ---------------------------------------------------------------------------
__device__ __forceinline__ float tf32_rn(float x) {
    uint32_t u;
    asm("cvt.rna.tf32.f32 %0, %1;" : "=r"(u) : "f"(x));
    return __uint_as_float(u);
}
__device__ __forceinline__ uint32_t smem_u32(const void* p) {
    uint32_t a;
    asm("{ .reg .u64 t; cvta.to.shared.u64 t, %1; cvt.u32.u64 %0, t; }" : "=r"(a) : "l"(p));
    return a;
}
#define CP_ASYNC16(dst, src) \
    asm volatile("cp.async.cg.shared.global [%0], [%1], 16;" :: "r"(dst), "l"(src))
#define CP_COMMIT() asm volatile("cp.async.commit_group;" ::: "memory")
#define CP_WAIT1()  asm volatile("cp.async.wait_group 1;" ::: "memory")
#define CP_WAIT0()  asm volatile("cp.async.wait_group 0;" ::: "memory")

// m16n8k8 tf32 mma: D += A*B. A row-major 16x8, B[k][n] (col), C/D fp32.
__device__ __forceinline__ void mma16n8k8(float* d, const float* a, const float* b) {
    asm volatile(
        "mma.sync.aligned.m16n8k8.row.col.f32.tf32.tf32.f32 "
        "{%0,%1,%2,%3}, {%4,%5,%6,%7}, {%8,%9}, {%0,%1,%2,%3};"
        : "+f"(d[0]), "+f"(d[1]), "+f"(d[2]), "+f"(d[3])
        : "r"(__float_as_uint(a[0])), "r"(__float_as_uint(a[1])),
          "r"(__float_as_uint(a[2])), "r"(__float_as_uint(a[3])),
          "r"(__float_as_uint(b[0])), "r"(__float_as_uint(b[1])));
}

// ---------------------------------------------------------------------------
// Tensor-core GEMM: Y = X @ W^T + bias.  CTA 128x128, 8 warps (2m x 4n), BK=16.
// mode 0: scatter into [b,h,s,d] head layout, tf32-RN-rounded (feeds attn mma)
// mode 1: plain [m][n] row-major fp32
// ---------------------------------------------------------------------------
__global__ __launch_bounds__(256, 2) void gemm_mma_kernel(
    const float* __restrict__ X, const float* __restrict__ W,
    const float* __restrict__ bias, float* __restrict__ Y, int mode)
{
    __shared__ __align__(16) float As[128][20];
    __shared__ __align__(16) float Bs[128][20];

    const int tid  = threadIdx.x;
    const int lane = tid & 31;
    const int wid  = tid >> 5;
    const int g = lane >> 2;
    const int t = lane & 3;
    const int wm = (wid >> 2) * 64;
    const int wn = (wid & 3) * 32;
    const int m0 = blockIdx.y * 128;
    const int n0 = blockIdx.x * 128;

    const int srow = tid >> 1;
    const int scol = (tid & 1) * 8;
    const float* Xp = X + (size_t)(m0 + srow) * DMODEL + scol;
    const float* Wp = W + (size_t)(n0 + srow) * DMODEL + scol;

    float acc[4][4][4] = {};

    for (int k0 = 0; k0 < DMODEL; k0 += 16) {
        float4 xa = *(const float4*)(Xp + k0);
        float4 xb = *(const float4*)(Xp + k0 + 4);
        float4 wa = *(const float4*)(Wp + k0);
        float4 wb = *(const float4*)(Wp + k0 + 4);
        __syncthreads();
        As[srow][scol + 0] = tf32_rn(xa.x); As[srow][scol + 1] = tf32_rn(xa.y);
        As[srow][scol + 2] = tf32_rn(xa.z); As[srow][scol + 3] = tf32_rn(xa.w);
        As[srow][scol + 4] = tf32_rn(xb.x); As[srow][scol + 5] = tf32_rn(xb.y);
        As[srow][scol + 6] = tf32_rn(xb.z); As[srow][scol + 7] = tf32_rn(xb.w);
        Bs[srow][scol + 0] = tf32_rn(wa.x); Bs[srow][scol + 1] = tf32_rn(wa.y);
        Bs[srow][scol + 2] = tf32_rn(wa.z); Bs[srow][scol + 3] = tf32_rn(wa.w);
        Bs[srow][scol + 4] = tf32_rn(wb.x); Bs[srow][scol + 5] = tf32_rn(wb.y);
        Bs[srow][scol + 6] = tf32_rn(wb.z); Bs[srow][scol + 7] = tf32_rn(wb.w);
        __syncthreads();

        #pragma unroll
        for (int kk = 0; kk < 16; kk += 8) {
            float a[4][4], b[4][2];
            #pragma unroll
            for (int mi = 0; mi < 4; mi++) {
                const int mr = wm + mi * 16;
                a[mi][0] = As[mr + g    ][kk + t];
                a[mi][1] = As[mr + g + 8][kk + t];
                a[mi][2] = As[mr + g    ][kk + t + 4];
                a[mi][3] = As[mr + g + 8][kk + t + 4];
            }
            #pragma unroll
            for (int ni = 0; ni < 4; ni++) {
                const int nr = wn + ni * 8 + g;
                b[ni][0] = Bs[nr][kk + t];
                b[ni][1] = Bs[nr][kk + t + 4];
            }
            #pragma unroll
            for (int mi = 0; mi < 4; mi++)
                #pragma unroll
                for (int ni = 0; ni < 4; ni++)
                    mma16n8k8(acc[mi][ni], a[mi], b[ni]);
        }
    }

    #pragma unroll
    for (int mi = 0; mi < 4; mi++) {
        #pragma unroll
        for (int ni = 0; ni < 4; ni++) {
            const int n = n0 + wn + ni * 8 + 2 * t;
            const float bx = bias[n], by = bias[n + 1];
            #pragma unroll
            for (int half = 0; half < 2; half++) {
                const int m = m0 + wm + mi * 16 + g + half * 8;
                float2 o;
                o.x = acc[mi][ni][half * 2 + 0] + bx;
                o.y = acc[mi][ni][half * 2 + 1] + by;
                if (mode == 0) {
                    o.x = tf32_rn(o.x);      // Q/K/V feed tf32 mma in attention
                    o.y = tf32_rn(o.y);
                    const int bb = m >> 11;
                    const int s  = m & 2047;
                    const int h  = n >> 6;
                    size_t idx = (((size_t)(bb * NH + h) * S_LEN + s) * DK) + (size_t)(n & 63);
                    *(float2*)&Y[idx] = o;
                } else {
                    *(float2*)&Y[(size_t)m * DMODEL + n] = o;
                }
            }
        }
    }
}

// ---------------------------------------------------------------------------
// Tensor-core flash attention v3.
// CTA = one (b,h) x 128 q-rows; 4 warps x 32 q-rows (mi=2); kv-tiles of 64.
// Q fragments in registers (LDG prologue). K/V double-buffered via cp.async.
// P stays in registers: quad shuffle-transpose acc-layout -> A-frag layout.
// 2 barriers per tile. smem: Kb[2][64][68] + Vb[2][64][72] = 70 KB.
// ---------------------------------------------------------------------------
#define NT     (S_LEN / 64)                       // 32 kv-tiles
#define K_STR  68
#define V_STR  72
#define ATT_SMEM ((2*64*K_STR + 2*64*V_STR) * 4)  // 71680 B

__global__ __launch_bounds__(128, 2) void attn_mma_kernel(float* __restrict__ AO)
{
    extern __shared__ __align__(16) float sm[];
    float (*Kb)[K_STR] = (float(*)[K_STR])sm;                    // 2x64 rows
    float (*Vb)[V_STR] = (float(*)[V_STR])(sm + 2*64*K_STR);     // 2x64 rows
    const uint32_t skb = smem_u32(sm);
    const uint32_t svb = skb + 2*64*K_STR*4;

    const int tid  = threadIdx.x;
    const int lane = tid & 31;
    const int wid  = tid >> 5;          // 0..3
    const int g = lane >> 2;            // 0..7
    const int t = lane & 3;             // 0..3
    const int q0 = blockIdx.x * 128;
    const int bh = blockIdx.y;
    const int mr = wid * 32;

    const float* Qg = g_Q + (size_t)bh * S_LEN * DK;
    const float* Kg = g_K + (size_t)bh * S_LEN * DK;
    const float* Vg = g_V + (size_t)bh * S_LEN * DK;

    // kv tile loader: one cp.async commit group per tile
    const int lrow = tid >> 1;
    const int lcb  = (tid & 1) * 32;
    auto load_tile = [&](int j, int buf) {
        const float* kp = Kg + (size_t)(j * 64 + lrow) * DK + lcb;
        const float* vp = Vg + (size_t)(j * 64 + lrow) * DK + lcb;
        const uint32_t kd = skb + (uint32_t)(buf * 64 * K_STR + lrow * K_STR + lcb) * 4;
        const uint32_t vd = svb + (uint32_t)(buf * 64 * V_STR + lrow * V_STR + lcb) * 4;
        #pragma unroll
        for (int i = 0; i < 8; i++) {
            CP_ASYNC16(kd + i * 16, kp + i * 4);
            CP_ASYNC16(vd + i * 16, vp + i * 4);
        }
        CP_COMMIT();
    };

    load_tile(0, 0);
    load_tile(1, 1);

    // Q fragments straight from gmem (each element read exactly once)
    float qf[2][8][4];
    {
        const float* qb = Qg + (size_t)(q0 + mr) * DK;
        #pragma unroll
        for (int mi = 0; mi < 2; mi++) {
            const int r0 = (mi * 16 + g) * DK;
            const int r1 = (mi * 16 + g + 8) * DK;
            #pragma unroll
            for (int kk8 = 0; kk8 < 8; kk8++) {
                const int c = kk8 * 8 + t;
                qf[mi][kk8][0] = qb[r0 + c];
                qf[mi][kk8][1] = qb[r1 + c];
                qf[mi][kk8][2] = qb[r0 + c + 4];
                qf[mi][kk8][3] = qb[r1 + c + 4];
            }
        }
    }

    float oacc[2][8][4] = {};
    float mrow[2][2], lrow2[2][2];
    #pragma unroll
    for (int mi = 0; mi < 2; mi++)
        #pragma unroll
        for (int hf = 0; hf < 2; hf++) { mrow[mi][hf] = -1e30f; lrow2[mi][hf] = 0.f; }

    const uint32_t FULL = 0xffffffffu;
    const int srcA = (lane & ~3) | (t >> 1);      // quad lane holding cols {t&~1, |1}
    const int srcB = srcA + 2;                    // quad lane holding cols {+4, +5}

    for (int j = 0; j < NT; j++) {
        const int buf = j & 1;
        if (j == NT - 1) { CP_WAIT0(); } else { CP_WAIT1(); }
        __syncthreads();                          // tile j visible to all warps

        const float (*Ks)[K_STR] = Kb + buf * 64;
        const float (*Vs)[V_STR] = Vb + buf * 64;

        // scores: S = Q K^T  (warp: 32 rows x 64 keys)
        float sacc[2][8][4] = {};
        #pragma unroll
        for (int kk8 = 0; kk8 < 8; kk8++) {
            const int kc = kk8 * 8 + t;
            float b[8][2];
            #pragma unroll
            for (int ni = 0; ni < 8; ni++) {
                b[ni][0] = Ks[ni * 8 + g][kc];
                b[ni][1] = Ks[ni * 8 + g][kc + 4];
            }
            #pragma unroll
            for (int ni = 0; ni < 8; ni++)
                #pragma unroll
                for (int mi = 0; mi < 2; mi++)
                    mma16n8k8(sacc[mi][ni], qf[mi][kk8], b[ni]);
        }

        // online softmax (row lives in a lane quad -> 2 shfls per reduction)
        #pragma unroll
        for (int mi = 0; mi < 2; mi++) {
            #pragma unroll
            for (int hf = 0; hf < 2; hf++) {
                float mx = -1e30f;
                #pragma unroll
                for (int ni = 0; ni < 8; ni++) {
                    sacc[mi][ni][hf * 2 + 0] *= 0.125f;
                    sacc[mi][ni][hf * 2 + 1] *= 0.125f;
                    mx = fmaxf(mx, fmaxf(sacc[mi][ni][hf * 2], sacc[mi][ni][hf * 2 + 1]));
                }
                mx = fmaxf(mx, __shfl_xor_sync(FULL, mx, 1));
                mx = fmaxf(mx, __shfl_xor_sync(FULL, mx, 2));
                const float mnew = fmaxf(mrow[mi][hf], mx);
                const float alpha = __expf(mrow[mi][hf] - mnew);
                mrow[mi][hf] = mnew;
                float sum = 0.f;
                #pragma unroll
                for (int ni = 0; ni < 8; ni++) {
                    float p0 = __expf(sacc[mi][ni][hf * 2 + 0] - mnew);
                    float p1 = __expf(sacc[mi][ni][hf * 2 + 1] - mnew);
                    sacc[mi][ni][hf * 2 + 0] = p0;
                    sacc[mi][ni][hf * 2 + 1] = p1;
                    sum += p0 + p1;
                }
                sum += __shfl_xor_sync(FULL, sum, 1);
                sum += __shfl_xor_sync(FULL, sum, 2);
                lrow2[mi][hf] = lrow2[mi][hf] * alpha + sum;
                #pragma unroll
                for (int ni = 0; ni < 8; ni++) {
                    oacc[mi][ni][hf * 2 + 0] *= alpha;
                    oacc[mi][ni][hf * 2 + 1] *= alpha;
                }
            }
        }

        // in-register transpose: acc layout (cols 2t,2t+1) -> A-frag (cols t,t+4)
        // af0=P[g][t] af1=P[g+8][t] af2=P[g][t+4] af3=P[g+8][t+4]
        #pragma unroll
        for (int mi = 0; mi < 2; mi++) {
            #pragma unroll
            for (int ni = 0; ni < 8; ni++) {
                float c0 = tf32_rn(sacc[mi][ni][0]);
                float c1 = tf32_rn(sacc[mi][ni][1]);
                float c2 = tf32_rn(sacc[mi][ni][2]);
                float c3 = tf32_rn(sacc[mi][ni][3]);
                float x0 = __shfl_sync(FULL, c0, srcA);
                float x1 = __shfl_sync(FULL, c1, srcA);
                float y0 = __shfl_sync(FULL, c0, srcB);
                float y1 = __shfl_sync(FULL, c1, srcB);
                float z0 = __shfl_sync(FULL, c2, srcA);
                float z1 = __shfl_sync(FULL, c3, srcA);
                float w0 = __shfl_sync(FULL, c2, srcB);
                float w1 = __shfl_sync(FULL, c3, srcB);
                sacc[mi][ni][0] = (t & 1) ? x1 : x0;
                sacc[mi][ni][1] = (t & 1) ? z1 : z0;
                sacc[mi][ni][2] = (t & 1) ? y1 : y0;
                sacc[mi][ni][3] = (t & 1) ? w1 : w0;
            }
        }

        // O += P @ V   (A = transposed sacc frags; B = V^T from row-major Vs)
        #pragma unroll
        for (int kk8 = 0; kk8 < 8; kk8++) {
            const int kc = kk8 * 8 + t;
            float b[8][2];
            #pragma unroll
            for (int ni = 0; ni < 8; ni++) {
                b[ni][0] = Vs[kc    ][ni * 8 + g];
                b[ni][1] = Vs[kc + 4][ni * 8 + g];
            }
            #pragma unroll
            for (int ni = 0; ni < 8; ni++)
                #pragma unroll
                for (int mi = 0; mi < 2; mi++)
                    mma16n8k8(oacc[mi][ni], sacc[mi][kk8], b[ni]);
        }

        __syncthreads();                          // all warps done with buf
        if (j + 2 < NT) load_tile(j + 2, buf);
    }

    // epilogue: AO[b*S + s][h*64 + d] = O / l
    const int h = bh & (NH - 1);
    const int b = bh >> 4;
    #pragma unroll
    for (int mi = 0; mi < 2; mi++) {
        const float inv0 = 1.0f / lrow2[mi][0];
        const float inv1 = 1.0f / lrow2[mi][1];
        const int r0 = q0 + mr + mi * 16 + g;
        #pragma unroll
        for (int ni = 0; ni < 8; ni++) {
            const int d = ni * 8 + 2 * t;
            size_t i0 = ((size_t)(b * S_LEN + r0    )) * DMODEL + (size_t)(h * DK + d);
            size_t i1 = ((size_t)(b * S_LEN + r0 + 8)) * DMODEL + (size_t)(h * DK + d);
            *(float2*)&AO[i0] = make_float2(oacc[mi][ni][0] * inv0, oacc[mi][ni][1] * inv0);
            *(float2*)&AO[i1] = make_float2(oacc[mi][ni][2] * inv1, oacc[mi][ni][3] * inv1);
        }
    }
}

// ---------------------------------------------------------------------------
extern "C" void kernel_launch(void* const* d_in, const int* in_sizes, int n_in,
                              void* d_out, int out_size)
{
    (void)in_sizes; (void)n_in; (void)out_size;
    const float* q  = (const float*)d_in[0];
    const float* k  = (const float*)d_in[1];
    const float* v  = (const float*)d_in[2];
    const float* Wq = (const float*)d_in[3];
    const float* bq = (const float*)d_in[4];
    const float* Wk = (const float*)d_in[5];
    const float* bk = (const float*)d_in[6];
    const float* Wv = (const float*)d_in[7];
    const float* bv = (const float*)d_in[8];
    const float* Wo = (const float*)d_in[9];
    const float* bo = (const float*)d_in[10];
    float* out = (float*)d_out;

    float *Qp, *Kp, *Vp, *AOp;
    cudaGetSymbolAddress((void**)&Qp,  g_Q);
    cudaGetSymbolAddress((void**)&Kp,  g_K);
    cudaGetSymbolAddress((void**)&Vp,  g_V);
    cudaGetSymbolAddress((void**)&AOp, g_AO);

    cudaFuncSetAttribute(attn_mma_kernel,
                         cudaFuncAttributeMaxDynamicSharedMemorySize, ATT_SMEM);

    dim3 ggrid(DMODEL / 128, M_TOT / 128);   // (8, 64)
    gemm_mma_kernel<<<ggrid, 256>>>(q, Wq, bq, Qp, 0);
    gemm_mma_kernel<<<ggrid, 256>>>(k, Wk, bk, Kp, 0);
    gemm_mma_kernel<<<ggrid, 256>>>(v, Wv, bv, Vp, 0);

    attn_mma_kernel<<<dim3(S_LEN / 128, BATCH * NH), 128, ATT_SMEM>>>(AOp);

    gemm_mma_kernel<<<ggrid, 256>>>(AOp, Wo, bo, out, 1);
}

// round 10
// speedup vs baseline: 3.0954x; 1.0883x over previous
#include <cuda_runtime.h>
#include <cstdint>
#include <math.h>

#define S_LEN  2048
#define DMODEL 1024
#define NH     16
#define DK     64
#define BATCH  4
#define M_TOT  (BATCH * S_LEN)   // 8192

// Scratch (static __device__ — no allocations allowed)
__device__ float g_Q[BATCH * NH * S_LEN * DK];   // [b,h,s,d] (tf32-rounded)
__device__ float g_K[BATCH * NH * S_LEN * DK];
__device__ float g_V[BATCH * NH * S_LEN * DK];
__device__ float g_AO[(size_t)M_TOT * DMODEL];   // attention out, [m][e] row-major

// ---------------------------------------------------------------------------
__device__ __forceinline__ float tf32_rn(float x) {
    uint32_t u;
    asm("cvt.rna.tf32.f32 %0, %1;" : "=r"(u) : "f"(x));
    return __uint_as_float(u);
}
__device__ __forceinline__ uint32_t smem_u32(const void* p) {
    uint32_t a;
    asm("{ .reg .u64 t; cvta.to.shared.u64 t, %1; cvt.u32.u64 %0, t; }" : "=r"(a) : "l"(p));
    return a;
}
#define CP_ASYNC16(dst, src) \
    asm volatile("cp.async.cg.shared.global [%0], [%1], 16;" :: "r"(dst), "l"(src))
#define CP_COMMIT() asm volatile("cp.async.commit_group;" ::: "memory")
#define CP_WAIT1()  asm volatile("cp.async.wait_group 1;" ::: "memory")
#define CP_WAIT0()  asm volatile("cp.async.wait_group 0;" ::: "memory")

// m16n8k8 tf32 mma: D += A*B. A row-major 16x8, B[k][n] (col), C/D fp32.
__device__ __forceinline__ void mma16n8k8(float* d, const float* a, const float* b) {
    asm volatile(
        "mma.sync.aligned.m16n8k8.row.col.f32.tf32.tf32.f32 "
        "{%0,%1,%2,%3}, {%4,%5,%6,%7}, {%8,%9}, {%0,%1,%2,%3};"
        : "+f"(d[0]), "+f"(d[1]), "+f"(d[2]), "+f"(d[3])
        : "r"(__float_as_uint(a[0])), "r"(__float_as_uint(a[1])),
          "r"(__float_as_uint(a[2])), "r"(__float_as_uint(a[3])),
          "r"(__float_as_uint(b[0])), "r"(__float_as_uint(b[1])));
}

// ---------------------------------------------------------------------------
// Tensor-core GEMM v2: Y = X @ W^T + bias.  CTA 128x128, 8 warps (2m x 4n).
// BK=16, 3-stage cp.async pipeline, ONE barrier per k-step.
// tf32 RN rounding applied at fragment-load time (same rounded values as
// staging-time rounding -> numerics identical to R5/R9 GEMM).
// mode 0: scatter into [b,h,s,d] head layout, tf32-RN-rounded outputs
// mode 1: plain [m][n] row-major fp32
// ---------------------------------------------------------------------------
#define GS 3
#define GEMM_SMEM (GS * 128 * 20 * 2 * 4)   // 61440 B

__global__ __launch_bounds__(256, 2) void gemm_mma_kernel(
    const float* __restrict__ X, const float* __restrict__ W,
    const float* __restrict__ bias, float* __restrict__ Y, int mode)
{
    extern __shared__ __align__(16) float gsm[];
    float (*As)[20] = (float(*)[20])gsm;                    // GS*128 rows
    float (*Bs)[20] = (float(*)[20])(gsm + GS * 128 * 20);  // GS*128 rows
    const uint32_t sA = smem_u32(gsm);
    const uint32_t sB = sA + GS * 128 * 20 * 4;

    const int tid  = threadIdx.x;
    const int lane = tid & 31;
    const int wid  = tid >> 5;
    const int g = lane >> 2;
    const int t = lane & 3;
    const int wm = (wid >> 2) * 64;
    const int wn = (wid & 3) * 32;
    const int m0 = blockIdx.y * 128;
    const int n0 = blockIdx.x * 128;

    // staging: each thread cp.asyncs 2x16B per matrix per stage
    const int srow = tid >> 1;
    const int scol = (tid & 1) * 8;
    const float* Xp = X + (size_t)(m0 + srow) * DMODEL + scol;
    const float* Wp = W + (size_t)(n0 + srow) * DMODEL + scol;

    auto load_stage = [&](int j, int st) {
        const float* xp = Xp + j * 16;
        const float* wp = Wp + j * 16;
        const uint32_t da = sA + (uint32_t)(st * 128 * 20 + srow * 20 + scol) * 4;
        const uint32_t db = sB + (uint32_t)(st * 128 * 20 + srow * 20 + scol) * 4;
        CP_ASYNC16(da, xp);      CP_ASYNC16(da + 16, xp + 4);
        CP_ASYNC16(db, wp);      CP_ASYNC16(db + 16, wp + 4);
        CP_COMMIT();
    };

    load_stage(0, 0);
    load_stage(1, 1);

    float acc[4][4][4] = {};

    for (int j = 0; j < DMODEL / 16; j++) {      // 64 k-steps
        const int st = j % GS;
        if (j == DMODEL / 16 - 1) { CP_WAIT0(); } else { CP_WAIT1(); }
        __syncthreads();   // stage j ready; all warps past step j-1
        if (j + 2 < DMODEL / 16) load_stage(j + 2, (j + 2) % GS);

        const float (*Aj)[20] = As + st * 128;
        const float (*Bj)[20] = Bs + st * 128;

        #pragma unroll
        for (int kk = 0; kk < 16; kk += 8) {
            float a[4][4], b[4][2];
            #pragma unroll
            for (int mi = 0; mi < 4; mi++) {
                const int mr = wm + mi * 16;
                a[mi][0] = tf32_rn(Aj[mr + g    ][kk + t]);
                a[mi][1] = tf32_rn(Aj[mr + g + 8][kk + t]);
                a[mi][2] = tf32_rn(Aj[mr + g    ][kk + t + 4]);
                a[mi][3] = tf32_rn(Aj[mr + g + 8][kk + t + 4]);
            }
            #pragma unroll
            for (int ni = 0; ni < 4; ni++) {
                const int nr = wn + ni * 8 + g;
                b[ni][0] = tf32_rn(Bj[nr][kk + t]);
                b[ni][1] = tf32_rn(Bj[nr][kk + t + 4]);
            }
            #pragma unroll
            for (int mi = 0; mi < 4; mi++)
                #pragma unroll
                for (int ni = 0; ni < 4; ni++)
                    mma16n8k8(acc[mi][ni], a[mi], b[ni]);
        }
    }

    #pragma unroll
    for (int mi = 0; mi < 4; mi++) {
        #pragma unroll
        for (int ni = 0; ni < 4; ni++) {
            const int n = n0 + wn + ni * 8 + 2 * t;
            const float bx = bias[n], by = bias[n + 1];
            #pragma unroll
            for (int half = 0; half < 2; half++) {
                const int m = m0 + wm + mi * 16 + g + half * 8;
                float2 o;
                o.x = acc[mi][ni][half * 2 + 0] + bx;
                o.y = acc[mi][ni][half * 2 + 1] + by;
                if (mode == 0) {
                    o.x = tf32_rn(o.x);      // Q/K/V feed tf32 mma in attention
                    o.y = tf32_rn(o.y);
                    const int bb = m >> 11;
                    const int s  = m & 2047;
                    const int h  = n >> 6;
                    size_t idx = (((size_t)(bb * NH + h) * S_LEN + s) * DK) + (size_t)(n & 63);
                    *(float2*)&Y[idx] = o;
                } else {
                    *(float2*)&Y[(size_t)m * DMODEL + n] = o;
                }
            }
        }
    }
}

// ---------------------------------------------------------------------------
// Tensor-core flash attention v3.1.
// CTA = one (b,h) x 128 q-rows; 4 warps x 32 q-rows (mi=2); kv-tiles of 64.
// Q fragments in registers, PRE-SCALED by 1/8 (exact on tf32 values) so the
// softmax hot path has no scale muls. K/V double-buffered cp.async.
// P stays in registers via quad shuffle-transpose. 2 barriers per tile.
// ---------------------------------------------------------------------------
#define NT     (S_LEN / 64)                       // 32 kv-tiles
#define K_STR  68
#define V_STR  72
#define ATT_SMEM ((2*64*K_STR + 2*64*V_STR) * 4)  // 71680 B

__global__ __launch_bounds__(128, 2) void attn_mma_kernel(float* __restrict__ AO)
{
    extern __shared__ __align__(16) float sm[];
    float (*Kb)[K_STR] = (float(*)[K_STR])sm;                    // 2x64 rows
    float (*Vb)[V_STR] = (float(*)[V_STR])(sm + 2*64*K_STR);     // 2x64 rows
    const uint32_t skb = smem_u32(sm);
    const uint32_t svb = skb + 2*64*K_STR*4;

    const int tid  = threadIdx.x;
    const int lane = tid & 31;
    const int wid  = tid >> 5;          // 0..3
    const int g = lane >> 2;            // 0..7
    const int t = lane & 3;             // 0..3
    const int q0 = blockIdx.x * 128;
    const int bh = blockIdx.y;
    const int mr = wid * 32;

    const float* Qg = g_Q + (size_t)bh * S_LEN * DK;
    const float* Kg = g_K + (size_t)bh * S_LEN * DK;
    const float* Vg = g_V + (size_t)bh * S_LEN * DK;

    const int lrow = tid >> 1;
    const int lcb  = (tid & 1) * 32;
    auto load_tile = [&](int j, int buf) {
        const float* kp = Kg + (size_t)(j * 64 + lrow) * DK + lcb;
        const float* vp = Vg + (size_t)(j * 64 + lrow) * DK + lcb;
        const uint32_t kd = skb + (uint32_t)(buf * 64 * K_STR + lrow * K_STR + lcb) * 4;
        const uint32_t vd = svb + (uint32_t)(buf * 64 * V_STR + lrow * V_STR + lcb) * 4;
        #pragma unroll
        for (int i = 0; i < 8; i++) {
            CP_ASYNC16(kd + i * 16, kp + i * 4);
            CP_ASYNC16(vd + i * 16, vp + i * 4);
        }
        CP_COMMIT();
    };

    load_tile(0, 0);
    load_tile(1, 1);

    // Q fragments, pre-scaled by 1/sqrt(dk)=0.125 (exact pow2 on tf32 values)
    float qf[2][8][4];
    {
        const float* qb = Qg + (size_t)(q0 + mr) * DK;
        #pragma unroll
        for (int mi = 0; mi < 2; mi++) {
            const int r0 = (mi * 16 + g) * DK;
            const int r1 = (mi * 16 + g + 8) * DK;
            #pragma unroll
            for (int kk8 = 0; kk8 < 8; kk8++) {
                const int c = kk8 * 8 + t;
                qf[mi][kk8][0] = 0.125f * qb[r0 + c];
                qf[mi][kk8][1] = 0.125f * qb[r1 + c];
                qf[mi][kk8][2] = 0.125f * qb[r0 + c + 4];
                qf[mi][kk8][3] = 0.125f * qb[r1 + c + 4];
            }
        }
    }

    float oacc[2][8][4] = {};
    float mrow[2][2], lrow2[2][2];
    #pragma unroll
    for (int mi = 0; mi < 2; mi++)
        #pragma unroll
        for (int hf = 0; hf < 2; hf++) { mrow[mi][hf] = -1e30f; lrow2[mi][hf] = 0.f; }

    const uint32_t FULL = 0xffffffffu;
    const int srcA = (lane & ~3) | (t >> 1);
    const int srcB = srcA + 2;

    for (int j = 0; j < NT; j++) {
        const int buf = j & 1;
        if (j == NT - 1) { CP_WAIT0(); } else { CP_WAIT1(); }
        __syncthreads();

        const float (*Ks)[K_STR] = Kb + buf * 64;
        const float (*Vs)[V_STR] = Vb + buf * 64;

        // scores: S = (Q/8) K^T
        float sacc[2][8][4] = {};
        #pragma unroll
        for (int kk8 = 0; kk8 < 8; kk8++) {
            const int kc = kk8 * 8 + t;
            float b[8][2];
            #pragma unroll
            for (int ni = 0; ni < 8; ni++) {
                b[ni][0] = Ks[ni * 8 + g][kc];
                b[ni][1] = Ks[ni * 8 + g][kc + 4];
            }
            #pragma unroll
            for (int ni = 0; ni < 8; ni++)
                #pragma unroll
                for (int mi = 0; mi < 2; mi++)
                    mma16n8k8(sacc[mi][ni], qf[mi][kk8], b[ni]);
        }

        // online softmax (no scale muls; row in lane quad -> 2 shfls)
        #pragma unroll
        for (int mi = 0; mi < 2; mi++) {
            #pragma unroll
            for (int hf = 0; hf < 2; hf++) {
                float mx = -1e30f;
                #pragma unroll
                for (int ni = 0; ni < 8; ni++)
                    mx = fmaxf(mx, fmaxf(sacc[mi][ni][hf * 2], sacc[mi][ni][hf * 2 + 1]));
                mx = fmaxf(mx, __shfl_xor_sync(FULL, mx, 1));
                mx = fmaxf(mx, __shfl_xor_sync(FULL, mx, 2));
                const float mnew = fmaxf(mrow[mi][hf], mx);
                const float alpha = __expf(mrow[mi][hf] - mnew);
                mrow[mi][hf] = mnew;
                float sum = 0.f;
                #pragma unroll
                for (int ni = 0; ni < 8; ni++) {
                    float p0 = __expf(sacc[mi][ni][hf * 2 + 0] - mnew);
                    float p1 = __expf(sacc[mi][ni][hf * 2 + 1] - mnew);
                    sacc[mi][ni][hf * 2 + 0] = p0;
                    sacc[mi][ni][hf * 2 + 1] = p1;
                    sum += p0 + p1;
                }
                sum += __shfl_xor_sync(FULL, sum, 1);
                sum += __shfl_xor_sync(FULL, sum, 2);
                lrow2[mi][hf] = lrow2[mi][hf] * alpha + sum;
                #pragma unroll
                for (int ni = 0; ni < 8; ni++) {
                    oacc[mi][ni][hf * 2 + 0] *= alpha;
                    oacc[mi][ni][hf * 2 + 1] *= alpha;
                }
            }
        }

        // in-register transpose: acc layout -> A-frag layout (tf32 RN applied)
        #pragma unroll
        for (int mi = 0; mi < 2; mi++) {
            #pragma unroll
            for (int ni = 0; ni < 8; ni++) {
                float c0 = tf32_rn(sacc[mi][ni][0]);
                float c1 = tf32_rn(sacc[mi][ni][1]);
                float c2 = tf32_rn(sacc[mi][ni][2]);
                float c3 = tf32_rn(sacc[mi][ni][3]);
                float x0 = __shfl_sync(FULL, c0, srcA);
                float x1 = __shfl_sync(FULL, c1, srcA);
                float y0 = __shfl_sync(FULL, c0, srcB);
                float y1 = __shfl_sync(FULL, c1, srcB);
                float z0 = __shfl_sync(FULL, c2, srcA);
                float z1 = __shfl_sync(FULL, c3, srcA);
                float w0 = __shfl_sync(FULL, c2, srcB);
                float w1 = __shfl_sync(FULL, c3, srcB);
                sacc[mi][ni][0] = (t & 1) ? x1 : x0;
                sacc[mi][ni][1] = (t & 1) ? z1 : z0;
                sacc[mi][ni][2] = (t & 1) ? y1 : y0;
                sacc[mi][ni][3] = (t & 1) ? w1 : w0;
            }
        }

        // O += P @ V
        #pragma unroll
        for (int kk8 = 0; kk8 < 8; kk8++) {
            const int kc = kk8 * 8 + t;
            float b[8][2];
            #pragma unroll
            for (int ni = 0; ni < 8; ni++) {
                b[ni][0] = Vs[kc    ][ni * 8 + g];
                b[ni][1] = Vs[kc + 4][ni * 8 + g];
            }
            #pragma unroll
            for (int ni = 0; ni < 8; ni++)
                #pragma unroll
                for (int mi = 0; mi < 2; mi++)
                    mma16n8k8(oacc[mi][ni], sacc[mi][kk8], b[ni]);
        }

        __syncthreads();
        if (j + 2 < NT) load_tile(j + 2, buf);
    }

    // epilogue
    const int h = bh & (NH - 1);
    const int b = bh >> 4;
    #pragma unroll
    for (int mi = 0; mi < 2; mi++) {
        const float inv0 = 1.0f / lrow2[mi][0];
        const float inv1 = 1.0f / lrow2[mi][1];
        const int r0 = q0 + mr + mi * 16 + g;
        #pragma unroll
        for (int ni = 0; ni < 8; ni++) {
            const int d = ni * 8 + 2 * t;
            size_t i0 = ((size_t)(b * S_LEN + r0    )) * DMODEL + (size_t)(h * DK + d);
            size_t i1 = ((size_t)(b * S_LEN + r0 + 8)) * DMODEL + (size_t)(h * DK + d);
            *(float2*)&AO[i0] = make_float2(oacc[mi][ni][0] * inv0, oacc[mi][ni][1] * inv0);
            *(float2*)&AO[i1] = make_float2(oacc[mi][ni][2] * inv1, oacc[mi][ni][3] * inv1);
        }
    }
}

// ---------------------------------------------------------------------------
extern "C" void kernel_launch(void* const* d_in, const int* in_sizes, int n_in,
                              void* d_out, int out_size)
{
    (void)in_sizes; (void)n_in; (void)out_size;
    const float* q  = (const float*)d_in[0];
    const float* k  = (const float*)d_in[1];
    const float* v  = (const float*)d_in[2];
    const float* Wq = (const float*)d_in[3];
    const float* bq = (const float*)d_in[4];
    const float* Wk = (const float*)d_in[5];
    const float* bk = (const float*)d_in[6];
    const float* Wv = (const float*)d_in[7];
    const float* bv = (const float*)d_in[8];
    const float* Wo = (const float*)d_in[9];
    const float* bo = (const float*)d_in[10];
    float* out = (float*)d_out;

    float *Qp, *Kp, *Vp, *AOp;
    cudaGetSymbolAddress((void**)&Qp,  g_Q);
    cudaGetSymbolAddress((void**)&Kp,  g_K);
    cudaGetSymbolAddress((void**)&Vp,  g_V);
    cudaGetSymbolAddress((void**)&AOp, g_AO);

    cudaFuncSetAttribute(gemm_mma_kernel,
                         cudaFuncAttributeMaxDynamicSharedMemorySize, GEMM_SMEM);
    cudaFuncSetAttribute(attn_mma_kernel,
                         cudaFuncAttributeMaxDynamicSharedMemorySize, ATT_SMEM);

    dim3 ggrid(DMODEL / 128, M_TOT / 128);   // (8, 64)
    gemm_mma_kernel<<<ggrid, 256, GEMM_SMEM>>>(q, Wq, bq, Qp, 0);
    gemm_mma_kernel<<<ggrid, 256, GEMM_SMEM>>>(k, Wk, bk, Kp, 0);
    gemm_mma_kernel<<<ggrid, 256, GEMM_SMEM>>>(v, Wv, bv, Vp, 0);

    attn_mma_kernel<<<dim3(S_LEN / 128, BATCH * NH), 128, ATT_SMEM>>>(AOp);

    gemm_mma_kernel<<<ggrid, 256, GEMM_SMEM>>>(AOp, Wo, bo, out, 1);
}

// round 11
// speedup vs baseline: 3.1582x; 1.0203x over previous
#include <cuda_runtime.h>
#include <cstdint>
#include <math.h>

#define S_LEN  2048
#define DMODEL 1024
#define NH     16
#define DK     64
#define BATCH  4
#define M_TOT  (BATCH * S_LEN)   // 8192

// Scratch (static __device__ — no allocations allowed)
// g_Q, g_K: [b,h,s,d] with d interleave-permuted within 8-groups (tf32-rounded)
// g_V:      [b,h,d,s] TRANSPOSED, s interleave-permuted within 8-groups
__device__ float g_Q[BATCH * NH * S_LEN * DK];
__device__ float g_K[BATCH * NH * S_LEN * DK];
__device__ float g_V[BATCH * NH * S_LEN * DK];
__device__ float g_AO[(size_t)M_TOT * DMODEL];   // attention out, [m][e] row-major

// interleave perm within an 8-group: 0,1,2,3,4,5,6,7 -> slots 0,2,4,6,1,3,5,7
#define PERM8(x) (((x) & ~7) | (((x) & 3) << 1) | ((((x) >> 2)) & 1))

// ---------------------------------------------------------------------------
__device__ __forceinline__ float tf32_rn(float x) {
    uint32_t u;
    asm("cvt.rna.tf32.f32 %0, %1;" : "=r"(u) : "f"(x));
    return __uint_as_float(u);
}
__device__ __forceinline__ float ex2f(float x) {
    float y;
    asm("ex2.approx.f32 %0, %1;" : "=f"(y) : "f"(x));
    return y;
}
__device__ __forceinline__ uint32_t smem_u32(const void* p) {
    uint32_t a;
    asm("{ .reg .u64 t; cvta.to.shared.u64 t, %1; cvt.u32.u64 %0, t; }" : "=r"(a) : "l"(p));
    return a;
}
#define CP_ASYNC16(dst, src) \
    asm volatile("cp.async.cg.shared.global [%0], [%1], 16;" :: "r"(dst), "l"(src))
#define CP_COMMIT() asm volatile("cp.async.commit_group;" ::: "memory")
#define CP_WAIT1()  asm volatile("cp.async.wait_group 1;" ::: "memory")
#define CP_WAIT0()  asm volatile("cp.async.wait_group 0;" ::: "memory")

// m16n8k8 tf32 mma: D += A*B. A row-major 16x8, B[k][n] (col), C/D fp32.
__device__ __forceinline__ void mma16n8k8(float* d, const float* a, const float* b) {
    asm volatile(
        "mma.sync.aligned.m16n8k8.row.col.f32.tf32.tf32.f32 "
        "{%0,%1,%2,%3}, {%4,%5,%6,%7}, {%8,%9}, {%0,%1,%2,%3};"
        : "+f"(d[0]), "+f"(d[1]), "+f"(d[2]), "+f"(d[3])
        : "r"(__float_as_uint(a[0])), "r"(__float_as_uint(a[1])),
          "r"(__float_as_uint(a[2])), "r"(__float_as_uint(a[3])),
          "r"(__float_as_uint(b[0])), "r"(__float_as_uint(b[1])));
}

// ---------------------------------------------------------------------------
// Tensor-core GEMM: Y = X @ W^T + bias.  CTA 128x128, 8 warps (2m x 4n).
// BK=16, 3-stage cp.async pipeline, one barrier per k-step.
// mode 0: Q/K head scatter, d-columns PERM8-interleaved, tf32-RN outputs
// mode 2: V head scatter TRANSPOSED [b,h,d,s], s PERM8-interleaved, tf32-RN
// mode 1: plain [m][n] row-major fp32
// ---------------------------------------------------------------------------
#define GS 3
#define GEMM_SMEM (GS * 128 * 20 * 2 * 4)   // 61440 B

__global__ __launch_bounds__(256, 2) void gemm_mma_kernel(
    const float* __restrict__ X, const float* __restrict__ W,
    const float* __restrict__ bias, float* __restrict__ Y, int mode)
{
    extern __shared__ __align__(16) float gsm[];
    float (*As)[20] = (float(*)[20])gsm;
    float (*Bs)[20] = (float(*)[20])(gsm + GS * 128 * 20);
    const uint32_t sA = smem_u32(gsm);
    const uint32_t sB = sA + GS * 128 * 20 * 4;

    const int tid  = threadIdx.x;
    const int lane = tid & 31;
    const int wid  = tid >> 5;
    const int g = lane >> 2;
    const int t = lane & 3;
    const int wm = (wid >> 2) * 64;
    const int wn = (wid & 3) * 32;
    const int m0 = blockIdx.y * 128;
    const int n0 = blockIdx.x * 128;

    const int srow = tid >> 1;
    const int scol = (tid & 1) * 8;
    const float* Xp = X + (size_t)(m0 + srow) * DMODEL + scol;
    const float* Wp = W + (size_t)(n0 + srow) * DMODEL + scol;

    auto load_stage = [&](int j, int st) {
        const float* xp = Xp + j * 16;
        const float* wp = Wp + j * 16;
        const uint32_t da = sA + (uint32_t)(st * 128 * 20 + srow * 20 + scol) * 4;
        const uint32_t db = sB + (uint32_t)(st * 128 * 20 + srow * 20 + scol) * 4;
        CP_ASYNC16(da, xp);      CP_ASYNC16(da + 16, xp + 4);
        CP_ASYNC16(db, wp);      CP_ASYNC16(db + 16, wp + 4);
        CP_COMMIT();
    };

    load_stage(0, 0);
    load_stage(1, 1);

    float acc[4][4][4] = {};

    for (int j = 0; j < DMODEL / 16; j++) {
        const int st = j % GS;
        if (j == DMODEL / 16 - 1) { CP_WAIT0(); } else { CP_WAIT1(); }
        __syncthreads();
        if (j + 2 < DMODEL / 16) load_stage(j + 2, (j + 2) % GS);

        const float (*Aj)[20] = As + st * 128;
        const float (*Bj)[20] = Bs + st * 128;

        #pragma unroll
        for (int kk = 0; kk < 16; kk += 8) {
            float a[4][4], b[4][2];
            #pragma unroll
            for (int mi = 0; mi < 4; mi++) {
                const int mr = wm + mi * 16;
                a[mi][0] = tf32_rn(Aj[mr + g    ][kk + t]);
                a[mi][1] = tf32_rn(Aj[mr + g + 8][kk + t]);
                a[mi][2] = tf32_rn(Aj[mr + g    ][kk + t + 4]);
                a[mi][3] = tf32_rn(Aj[mr + g + 8][kk + t + 4]);
            }
            #pragma unroll
            for (int ni = 0; ni < 4; ni++) {
                const int nr = wn + ni * 8 + g;
                b[ni][0] = tf32_rn(Bj[nr][kk + t]);
                b[ni][1] = tf32_rn(Bj[nr][kk + t + 4]);
            }
            #pragma unroll
            for (int mi = 0; mi < 4; mi++)
                #pragma unroll
                for (int ni = 0; ni < 4; ni++)
                    mma16n8k8(acc[mi][ni], a[mi], b[ni]);
        }
    }

    #pragma unroll
    for (int mi = 0; mi < 4; mi++) {
        #pragma unroll
        for (int ni = 0; ni < 4; ni++) {
            const int n = n0 + wn + ni * 8 + 2 * t;
            const float bx = bias[n], by = bias[n + 1];
            #pragma unroll
            for (int half = 0; half < 2; half++) {
                const int m = m0 + wm + mi * 16 + g + half * 8;
                float ox = acc[mi][ni][half * 2 + 0] + bx;
                float oy = acc[mi][ni][half * 2 + 1] + by;
                if (mode == 1) {
                    *(float2*)&Y[(size_t)m * DMODEL + n] = make_float2(ox, oy);
                } else {
                    ox = tf32_rn(ox);
                    oy = tf32_rn(oy);
                    const int bb = m >> 11;
                    const int s  = m & 2047;
                    const int h  = n >> 6;
                    if (mode == 0) {
                        const int d0 = n & 63;
                        size_t base = ((size_t)(bb * NH + h) * S_LEN + s) * DK;
                        Y[base + PERM8(d0)]     = ox;
                        Y[base + PERM8(d0 + 1)] = oy;
                    } else {   // mode 2: V transposed [b,h,d,s], s permuted
                        const int sp = PERM8(s);
                        size_t base = ((size_t)(bb * NH + h) * DK + (size_t)(n & 63)) * S_LEN;
                        Y[base + sp]         = ox;
                        Y[base + S_LEN + sp] = oy;
                    }
                }
            }
        }
    }
}

// ---------------------------------------------------------------------------
// Tensor-core flash attention v4.
// CTA = one (b,h) x 128 q-rows; 4 warps x 32 q-rows; kv-tiles of 64.
// Key-interleave layout: K tile rows placed at PERM8 slots -> score acc
// registers ARE the PV A-fragment (zero-shuffle P handoff). Q/K d-columns
// and V s-columns PERM8-permuted in gmem -> all B-frags are LDS.64.
// exp2-domain softmax (log2e folded into Q scale). 2-stage cp.async.
// ---------------------------------------------------------------------------
#define NT     (S_LEN / 64)                 // 32 kv-tiles
#define K_STR  72
#define V_STR  72
#define ATT_SMEM ((2*64*K_STR + 2*64*V_STR) * 4)   // 73728 B

__global__ __launch_bounds__(128, 2) void attn_mma_kernel(float* __restrict__ AO)
{
    extern __shared__ __align__(16) float sm[];
    float (*Kb)[K_STR] = (float(*)[K_STR])sm;                  // 2x64 rows (key slots)
    float (*Vb)[V_STR] = (float(*)[V_STR])(sm + 2*64*K_STR);   // 2x64 rows (d)
    const uint32_t skb = smem_u32(sm);
    const uint32_t svb = skb + 2*64*K_STR*4;

    const int tid  = threadIdx.x;
    const int lane = tid & 31;
    const int wid  = tid >> 5;          // 0..3
    const int g = lane >> 2;            // 0..7
    const int t = lane & 3;             // 0..3
    const int q0 = blockIdx.x * 128;
    const int bh = blockIdx.y;
    const int mr = wid * 32;

    const float* Qg = g_Q + (size_t)bh * S_LEN * DK;
    const float* Kg = g_K + (size_t)bh * S_LEN * DK;
    const float* Vg = g_V + (size_t)bh * DK * S_LEN;   // transposed [d][s-slot]

    const int lrow = tid >> 1;          // 0..63
    const int lcb  = (tid & 1) * 32;
    const int krow = PERM8(lrow);       // K row placement: key s -> slot PERM8(s)
    auto load_tile = [&](int j, int buf) {
        const float* kp = Kg + (size_t)(j * 64 + lrow) * DK + lcb;
        const float* vp = Vg + (size_t)lrow * S_LEN + j * 64 + lcb;
        const uint32_t kd = skb + (uint32_t)(buf * 64 * K_STR + krow * K_STR + lcb) * 4;
        const uint32_t vd = svb + (uint32_t)(buf * 64 * V_STR + lrow * V_STR + lcb) * 4;
        #pragma unroll
        for (int i = 0; i < 8; i++) {
            CP_ASYNC16(kd + i * 16, kp + i * 4);
            CP_ASYNC16(vd + i * 16, vp + i * 4);
        }
        CP_COMMIT();
    };

    load_tile(0, 0);
    load_tile(1, 1);

    // Q fragments (gmem d-permuted -> LDG.64 pairs), scaled by log2e/8,
    // re-rounded to tf32 so mma inputs stay unbiased.
    const float SC = 0.125f * 1.4426950408889634f;
    float qf[2][8][4];
    {
        const float* qb = Qg + (size_t)(q0 + mr) * DK;
        #pragma unroll
        for (int mi = 0; mi < 2; mi++) {
            const float* r0 = qb + (size_t)(mi * 16 + g) * DK;
            const float* r1 = qb + (size_t)(mi * 16 + g + 8) * DK;
            #pragma unroll
            for (int kk8 = 0; kk8 < 8; kk8++) {
                const int c = kk8 * 8 + 2 * t;
                float2 u0 = *(const float2*)(r0 + c);
                float2 u1 = *(const float2*)(r1 + c);
                qf[mi][kk8][0] = tf32_rn(SC * u0.x);
                qf[mi][kk8][1] = tf32_rn(SC * u1.x);
                qf[mi][kk8][2] = tf32_rn(SC * u0.y);
                qf[mi][kk8][3] = tf32_rn(SC * u1.y);
            }
        }
    }

    float oacc[2][8][4] = {};
    float mrow[2][2], lrow2[2][2];
    #pragma unroll
    for (int mi = 0; mi < 2; mi++)
        #pragma unroll
        for (int hf = 0; hf < 2; hf++) { mrow[mi][hf] = -1e30f; lrow2[mi][hf] = 0.f; }

    const uint32_t FULL = 0xffffffffu;

    for (int j = 0; j < NT; j++) {
        const int buf = j & 1;
        if (j == NT - 1) { CP_WAIT0(); } else { CP_WAIT1(); }
        __syncthreads();

        const float (*Ks)[K_STR] = Kb + buf * 64;
        const float (*Vs)[V_STR] = Vb + buf * 64;

        // scores (log2 domain): S' = (Q*log2e/8) K^T
        float sacc[2][8][4] = {};
        #pragma unroll
        for (int kk8 = 0; kk8 < 8; kk8++) {
            const int kc = kk8 * 8 + 2 * t;
            float b[8][2];
            #pragma unroll
            for (int ni = 0; ni < 8; ni++) {
                float2 kb2 = *(const float2*)&Ks[ni * 8 + g][kc];
                b[ni][0] = kb2.x;
                b[ni][1] = kb2.y;
            }
            #pragma unroll
            for (int ni = 0; ni < 8; ni++)
                #pragma unroll
                for (int mi = 0; mi < 2; mi++)
                    mma16n8k8(sacc[mi][ni], qf[mi][kk8], b[ni]);
        }

        // online softmax, base-2 (row in lane quad -> 2 shfls per reduction)
        #pragma unroll
        for (int mi = 0; mi < 2; mi++) {
            #pragma unroll
            for (int hf = 0; hf < 2; hf++) {
                float mx = -1e30f;
                #pragma unroll
                for (int ni = 0; ni < 8; ni++)
                    mx = fmaxf(mx, fmaxf(sacc[mi][ni][hf * 2], sacc[mi][ni][hf * 2 + 1]));
                mx = fmaxf(mx, __shfl_xor_sync(FULL, mx, 1));
                mx = fmaxf(mx, __shfl_xor_sync(FULL, mx, 2));
                const float mnew = fmaxf(mrow[mi][hf], mx);
                const float alpha = ex2f(mrow[mi][hf] - mnew);
                mrow[mi][hf] = mnew;
                float sum = 0.f;
                #pragma unroll
                for (int ni = 0; ni < 8; ni++) {
                    float p0 = ex2f(sacc[mi][ni][hf * 2 + 0] - mnew);
                    float p1 = ex2f(sacc[mi][ni][hf * 2 + 1] - mnew);
                    sacc[mi][ni][hf * 2 + 0] = p0;
                    sacc[mi][ni][hf * 2 + 1] = p1;
                    sum += p0 + p1;
                }
                sum += __shfl_xor_sync(FULL, sum, 1);
                sum += __shfl_xor_sync(FULL, sum, 2);
                lrow2[mi][hf] = lrow2[mi][hf] * alpha + sum;
                #pragma unroll
                for (int ni = 0; ni < 8; ni++) {
                    oacc[mi][ni][hf * 2 + 0] *= alpha;
                    oacc[mi][ni][hf * 2 + 1] *= alpha;
                }
            }
        }

        // O += P @ V : key-interleaved layout makes the score accumulator the
        // PV A-fragment directly (a = {c0, c2, c1, c3}); B-frags are LDS.64.
        #pragma unroll
        for (int kk8 = 0; kk8 < 8; kk8++) {
            const int kc = kk8 * 8 + 2 * t;
            float b[8][2];
            #pragma unroll
            for (int ni = 0; ni < 8; ni++) {
                float2 vb2 = *(const float2*)&Vs[ni * 8 + g][kc];
                b[ni][0] = vb2.x;
                b[ni][1] = vb2.y;
            }
            float a[2][4];
            #pragma unroll
            for (int mi = 0; mi < 2; mi++) {
                a[mi][0] = tf32_rn(sacc[mi][kk8][0]);
                a[mi][1] = tf32_rn(sacc[mi][kk8][2]);
                a[mi][2] = tf32_rn(sacc[mi][kk8][1]);
                a[mi][3] = tf32_rn(sacc[mi][kk8][3]);
            }
            #pragma unroll
            for (int ni = 0; ni < 8; ni++)
                #pragma unroll
                for (int mi = 0; mi < 2; mi++)
                    mma16n8k8(oacc[mi][ni], a[mi], b[ni]);
        }

        __syncthreads();
        if (j + 2 < NT) load_tile(j + 2, buf);
    }

    // epilogue: AO[b*S + s][h*64 + d] = O / l   (oacc d-layout is natural)
    const int h = bh & (NH - 1);
    const int b = bh >> 4;
    #pragma unroll
    for (int mi = 0; mi < 2; mi++) {
        const float inv0 = 1.0f / lrow2[mi][0];
        const float inv1 = 1.0f / lrow2[mi][1];
        const int r0 = q0 + mr + mi * 16 + g;
        #pragma unroll
        for (int ni = 0; ni < 8; ni++) {
            const int d = ni * 8 + 2 * t;
            size_t i0 = ((size_t)(b * S_LEN + r0    )) * DMODEL + (size_t)(h * DK + d);
            size_t i1 = ((size_t)(b * S_LEN + r0 + 8)) * DMODEL + (size_t)(h * DK + d);
            *(float2*)&AO[i0] = make_float2(oacc[mi][ni][0] * inv0, oacc[mi][ni][1] * inv0);
            *(float2*)&AO[i1] = make_float2(oacc[mi][ni][2] * inv1, oacc[mi][ni][3] * inv1);
        }
    }
}

// ---------------------------------------------------------------------------
extern "C" void kernel_launch(void* const* d_in, const int* in_sizes, int n_in,
                              void* d_out, int out_size)
{
    (void)in_sizes; (void)n_in; (void)out_size;
    const float* q  = (const float*)d_in[0];
    const float* k  = (const float*)d_in[1];
    const float* v  = (const float*)d_in[2];
    const float* Wq = (const float*)d_in[3];
    const float* bq = (const float*)d_in[4];
    const float* Wk = (const float*)d_in[5];
    const float* bk = (const float*)d_in[6];
    const float* Wv = (const float*)d_in[7];
    const float* bv = (const float*)d_in[8];
    const float* Wo = (const float*)d_in[9];
    const float* bo = (const float*)d_in[10];
    float* out = (float*)d_out;

    float *Qp, *Kp, *Vp, *AOp;
    cudaGetSymbolAddress((void**)&Qp,  g_Q);
    cudaGetSymbolAddress((void**)&Kp,  g_K);
    cudaGetSymbolAddress((void**)&Vp,  g_V);
    cudaGetSymbolAddress((void**)&AOp, g_AO);

    cudaFuncSetAttribute(gemm_mma_kernel,
                         cudaFuncAttributeMaxDynamicSharedMemorySize, GEMM_SMEM);
    cudaFuncSetAttribute(attn_mma_kernel,
                         cudaFuncAttributeMaxDynamicSharedMemorySize, ATT_SMEM);

    dim3 ggrid(DMODEL / 128, M_TOT / 128);   // (8, 64)
    gemm_mma_kernel<<<ggrid, 256, GEMM_SMEM>>>(q, Wq, bq, Qp, 0);
    gemm_mma_kernel<<<ggrid, 256, GEMM_SMEM>>>(k, Wk, bk, Kp, 0);
    gemm_mma_kernel<<<ggrid, 256, GEMM_SMEM>>>(v, Wv, bv, Vp, 2);

    attn_mma_kernel<<<dim3(S_LEN / 128, BATCH * NH), 128, ATT_SMEM>>>(AOp);

    gemm_mma_kernel<<<ggrid, 256, GEMM_SMEM>>>(AOp, Wo, bo, out, 1);
}

// round 12
// speedup vs baseline: 3.1902x; 1.0101x over previous
#include <cuda_runtime.h>
#include <cstdint>
#include <math.h>

#define S_LEN  2048
#define DMODEL 1024
#define NH     16
#define DK     64
#define BATCH  4
#define M_TOT  (BATCH * S_LEN)   // 8192

// Scratch (static __device__ — no allocations allowed)
// g_Q, g_K: [b,h,s,d], d PERM8-interleaved (tf32-rounded)
// g_V:      [b,h,d,s] transposed, s PERM8-interleaved (tf32-rounded)
// g_rX[i]:  rounded + k-PERM8'd activation inputs (q,k,v)
// g_rW[i]:  rounded + k-PERM8'd weights (Wq,Wk,Wv,Wo)
// g_AO:     attention out [m][e], e PERM8-interleaved, tf32-rounded
__device__ float g_Q[BATCH * NH * S_LEN * DK];
__device__ float g_K[BATCH * NH * S_LEN * DK];
__device__ float g_V[BATCH * NH * S_LEN * DK];
__device__ float g_rX0[(size_t)M_TOT * DMODEL];
__device__ float g_rX1[(size_t)M_TOT * DMODEL];
__device__ float g_rX2[(size_t)M_TOT * DMODEL];
__device__ float g_rW[4][(size_t)DMODEL * DMODEL];
__device__ float g_AO[(size_t)M_TOT * DMODEL];

// interleave perm within an 8-group: 0..7 -> 0,2,4,6,1,3,5,7
#define PERM8(x) (((x) & ~7) | (((x) & 3) << 1) | ((((x) >> 2)) & 1))

// ---------------------------------------------------------------------------
__device__ __forceinline__ float tf32_rn(float x) {
    uint32_t u;
    asm("cvt.rna.tf32.f32 %0, %1;" : "=r"(u) : "f"(x));
    return __uint_as_float(u);
}
__device__ __forceinline__ float ex2f(float x) {
    float y;
    asm("ex2.approx.f32 %0, %1;" : "=f"(y) : "f"(x));
    return y;
}
__device__ __forceinline__ uint32_t smem_u32(const void* p) {
    uint32_t a;
    asm("{ .reg .u64 t; cvta.to.shared.u64 t, %1; cvt.u32.u64 %0, t; }" : "=r"(a) : "l"(p));
    return a;
}
#define CP_ASYNC16(dst, src) \
    asm volatile("cp.async.cg.shared.global [%0], [%1], 16;" :: "r"(dst), "l"(src))
#define CP_COMMIT() asm volatile("cp.async.commit_group;" ::: "memory")
#define CP_WAIT1()  asm volatile("cp.async.wait_group 1;" ::: "memory")
#define CP_WAIT0()  asm volatile("cp.async.wait_group 0;" ::: "memory")

__device__ __forceinline__ void mma16n8k8(float* d, const float* a, const float* b) {
    asm volatile(
        "mma.sync.aligned.m16n8k8.row.col.f32.tf32.tf32.f32 "
        "{%0,%1,%2,%3}, {%4,%5,%6,%7}, {%8,%9}, {%0,%1,%2,%3};"
        : "+f"(d[0]), "+f"(d[1]), "+f"(d[2]), "+f"(d[3])
        : "r"(__float_as_uint(a[0])), "r"(__float_as_uint(a[1])),
          "r"(__float_as_uint(a[2])), "r"(__float_as_uint(a[3])),
          "r"(__float_as_uint(b[0])), "r"(__float_as_uint(b[1])));
}

// ---------------------------------------------------------------------------
// Prepass: round to tf32 (RN) and PERM8-interleave the k dimension.
// Each thread handles one 8-float group: out slots 0..7 = orig 0,4,1,5,2,6,3,7.
// Up to 4 (src,dst) pairs selected by blockIdx.z.
// ---------------------------------------------------------------------------
__global__ void prep_kernel(const float* __restrict__ s0, const float* __restrict__ s1,
                            const float* __restrict__ s2, const float* __restrict__ s3,
                            float* __restrict__ d0, float* __restrict__ d1,
                            float* __restrict__ d2, float* __restrict__ d3, int n8)
{
    int i = blockIdx.x * blockDim.x + threadIdx.x;
    if (i >= n8) return;
    const int z = blockIdx.z;
    const float* s = (z == 0) ? s0 : (z == 1) ? s1 : (z == 2) ? s2 : s3;
    float*       d = (z == 0) ? d0 : (z == 1) ? d1 : (z == 2) ? d2 : d3;
    float4 u0 = *(const float4*)(s + (size_t)i * 8);
    float4 u1 = *(const float4*)(s + (size_t)i * 8 + 4);
    float4 o0 = make_float4(tf32_rn(u0.x), tf32_rn(u1.x), tf32_rn(u0.y), tf32_rn(u1.y));
    float4 o1 = make_float4(tf32_rn(u0.z), tf32_rn(u1.z), tf32_rn(u0.w), tf32_rn(u1.w));
    *(float4*)(d + (size_t)i * 8)     = o0;
    *(float4*)(d + (size_t)i * 8 + 4) = o1;
}

// ---------------------------------------------------------------------------
// Tensor-core GEMM v3: Y = X @ W^T + bias.  CTA 128x128, 8 warps (2m x 4n).
// Operands pre-rounded + k-PERM8'd in gmem -> inner loop is 12 LDS.64 + 16 mma
// per k8 step, zero cvt. Stride-24 smem: conflict-free LDS.64 frags.
// BK=16, 3-stage cp.async pipeline, one barrier per k-step.
// mode 0: Q/K head scatter (d PERM8'd); mode 2: V transposed scatter;
// mode 1: plain [m][n] fp32.
// ---------------------------------------------------------------------------
#define GS 3
#define A_STR 24
#define GEMM_SMEM (GS * 128 * A_STR * 2 * 4)   // 73728 B

__global__ __launch_bounds__(256, 2) void gemm_mma_kernel(
    const float* __restrict__ X, const float* __restrict__ W,
    const float* __restrict__ bias, float* __restrict__ Y, int mode)
{
    extern __shared__ __align__(16) float gsm[];
    float (*As)[A_STR] = (float(*)[A_STR])gsm;
    float (*Bs)[A_STR] = (float(*)[A_STR])(gsm + GS * 128 * A_STR);
    const uint32_t sA = smem_u32(gsm);
    const uint32_t sB = sA + GS * 128 * A_STR * 4;

    const int tid  = threadIdx.x;
    const int lane = tid & 31;
    const int wid  = tid >> 5;
    const int g = lane >> 2;
    const int t = lane & 3;
    const int wm = (wid >> 2) * 64;
    const int wn = (wid & 3) * 32;
    const int m0 = blockIdx.y * 128;
    const int n0 = blockIdx.x * 128;

    const int srow = tid >> 1;
    const int scol = (tid & 1) * 8;
    const float* Xp = X + (size_t)(m0 + srow) * DMODEL + scol;
    const float* Wp = W + (size_t)(n0 + srow) * DMODEL + scol;

    auto load_stage = [&](int j, int st) {
        const float* xp = Xp + j * 16;
        const float* wp = Wp + j * 16;
        const uint32_t da = sA + (uint32_t)(st * 128 * A_STR + srow * A_STR + scol) * 4;
        const uint32_t db = sB + (uint32_t)(st * 128 * A_STR + srow * A_STR + scol) * 4;
        CP_ASYNC16(da, xp);      CP_ASYNC16(da + 16, xp + 4);
        CP_ASYNC16(db, wp);      CP_ASYNC16(db + 16, wp + 4);
        CP_COMMIT();
    };

    load_stage(0, 0);
    load_stage(1, 1);

    float acc[4][4][4] = {};

    for (int j = 0; j < DMODEL / 16; j++) {
        const int st = j % GS;
        if (j == DMODEL / 16 - 1) { CP_WAIT0(); } else { CP_WAIT1(); }
        __syncthreads();
        if (j + 2 < DMODEL / 16) load_stage(j + 2, (j + 2) % GS);

        const float (*Aj)[A_STR] = As + st * 128;
        const float (*Bj)[A_STR] = Bs + st * 128;

        #pragma unroll
        for (int kk = 0; kk < 16; kk += 8) {
            const int kc = kk + 2 * t;    // slot pair (orig t, orig t+4)
            float a[4][4], b[4][2];
            #pragma unroll
            for (int mi = 0; mi < 4; mi++) {
                const int mr = wm + mi * 16;
                float2 lo = *(const float2*)&Aj[mr + g    ][kc];
                float2 hi = *(const float2*)&Aj[mr + g + 8][kc];
                a[mi][0] = lo.x; a[mi][1] = hi.x; a[mi][2] = lo.y; a[mi][3] = hi.y;
            }
            #pragma unroll
            for (int ni = 0; ni < 4; ni++) {
                float2 bb = *(const float2*)&Bj[wn + ni * 8 + g][kc];
                b[ni][0] = bb.x; b[ni][1] = bb.y;
            }
            #pragma unroll
            for (int mi = 0; mi < 4; mi++)
                #pragma unroll
                for (int ni = 0; ni < 4; ni++)
                    mma16n8k8(acc[mi][ni], a[mi], b[ni]);
        }
    }

    #pragma unroll
    for (int mi = 0; mi < 4; mi++) {
        #pragma unroll
        for (int ni = 0; ni < 4; ni++) {
            const int n = n0 + wn + ni * 8 + 2 * t;
            const float bx = bias[n], by = bias[n + 1];
            #pragma unroll
            for (int half = 0; half < 2; half++) {
                const int m = m0 + wm + mi * 16 + g + half * 8;
                float ox = acc[mi][ni][half * 2 + 0] + bx;
                float oy = acc[mi][ni][half * 2 + 1] + by;
                if (mode == 1) {
                    *(float2*)&Y[(size_t)m * DMODEL + n] = make_float2(ox, oy);
                } else {
                    ox = tf32_rn(ox);
                    oy = tf32_rn(oy);
                    const int bb = m >> 11;
                    const int s  = m & 2047;
                    const int h  = n >> 6;
                    if (mode == 0) {
                        const int d0 = n & 63;
                        size_t base = ((size_t)(bb * NH + h) * S_LEN + s) * DK;
                        Y[base + PERM8(d0)]     = ox;
                        Y[base + PERM8(d0 + 1)] = oy;
                    } else {   // mode 2: V transposed [b,h,d,s], s permuted
                        const int sp = PERM8(s);
                        size_t base = ((size_t)(bb * NH + h) * DK + (size_t)(n & 63)) * S_LEN;
                        Y[base + sp]         = ox;
                        Y[base + S_LEN + sp] = oy;
                    }
                }
            }
        }
    }
}

// ---------------------------------------------------------------------------
// Tensor-core flash attention v5.
// CTA = one (b,h) x 128 q-rows; 8 warps x 16 q-rows (mi=1); kv-tiles of 64.
// 256 threads -> 16 warps/SM at 2 CTAs (regs <= 128/thread target).
// Key-interleave: score acc IS the PV A-fragment. All B-frags LDS.64.
// exp2-domain softmax. 2-stage cp.async. AO written rounded + PERM8'd.
// ---------------------------------------------------------------------------
#define NT     (S_LEN / 64)
#define K_STR  72
#define V_STR  72
#define ATT_SMEM ((2*64*K_STR + 2*64*V_STR) * 4)   // 73728 B

__global__ __launch_bounds__(256, 2) void attn_mma_kernel(float* __restrict__ AO)
{
    extern __shared__ __align__(16) float sm[];
    float (*Kb)[K_STR] = (float(*)[K_STR])sm;
    float (*Vb)[V_STR] = (float(*)[V_STR])(sm + 2*64*K_STR);
    const uint32_t skb = smem_u32(sm);
    const uint32_t svb = skb + 2*64*K_STR*4;

    const int tid  = threadIdx.x;
    const int lane = tid & 31;
    const int wid  = tid >> 5;          // 0..7
    const int g = lane >> 2;
    const int t = lane & 3;
    const int q0 = blockIdx.x * 128;
    const int bh = blockIdx.y;
    const int mr = wid * 16;

    const float* Qg = g_Q + (size_t)bh * S_LEN * DK;
    const float* Kg = g_K + (size_t)bh * S_LEN * DK;
    const float* Vg = g_V + (size_t)bh * DK * S_LEN;

    const int lrow = tid >> 2;          // 0..63
    const int lcb  = (tid & 3) * 16;
    const int krow = PERM8(lrow);
    auto load_tile = [&](int j, int buf) {
        const float* kp = Kg + (size_t)(j * 64 + lrow) * DK + lcb;
        const float* vp = Vg + (size_t)lrow * S_LEN + j * 64 + lcb;
        const uint32_t kd = skb + (uint32_t)(buf * 64 * K_STR + krow * K_STR + lcb) * 4;
        const uint32_t vd = svb + (uint32_t)(buf * 64 * V_STR + lrow * V_STR + lcb) * 4;
        #pragma unroll
        for (int i = 0; i < 4; i++) {
            CP_ASYNC16(kd + i * 16, kp + i * 4);
            CP_ASYNC16(vd + i * 16, vp + i * 4);
        }
        CP_COMMIT();
    };

    load_tile(0, 0);
    load_tile(1, 1);

    // Q fragments (d-permuted gmem -> LDG.64), scaled by log2e/8, re-rounded.
    const float SC = 0.125f * 1.4426950408889634f;
    float qf[8][4];
    {
        const float* r0 = Qg + (size_t)(q0 + mr + g)     * DK;
        const float* r1 = Qg + (size_t)(q0 + mr + g + 8) * DK;
        #pragma unroll
        for (int kk8 = 0; kk8 < 8; kk8++) {
            const int c = kk8 * 8 + 2 * t;
            float2 u0 = *(const float2*)(r0 + c);
            float2 u1 = *(const float2*)(r1 + c);
            qf[kk8][0] = tf32_rn(SC * u0.x);
            qf[kk8][1] = tf32_rn(SC * u1.x);
            qf[kk8][2] = tf32_rn(SC * u0.y);
            qf[kk8][3] = tf32_rn(SC * u1.y);
        }
    }

    float oacc[8][4] = {};
    float mrow[2] = {-1e30f, -1e30f};
    float lrow2[2] = {0.f, 0.f};
    const uint32_t FULL = 0xffffffffu;

    for (int j = 0; j < NT; j++) {
        const int buf = j & 1;
        if (j == NT - 1) { CP_WAIT0(); } else { CP_WAIT1(); }
        __syncthreads();

        const float (*Ks)[K_STR] = Kb + buf * 64;
        const float (*Vs)[V_STR] = Vb + buf * 64;

        // scores (log2 domain)
        float sacc[8][4] = {};
        #pragma unroll
        for (int kk8 = 0; kk8 < 8; kk8++) {
            const int kc = kk8 * 8 + 2 * t;
            #pragma unroll
            for (int ni = 0; ni < 8; ni++) {
                float2 kb2 = *(const float2*)&Ks[ni * 8 + g][kc];
                float b2[2] = {kb2.x, kb2.y};
                mma16n8k8(sacc[ni], qf[kk8], b2);
            }
        }

        // online softmax, base-2
        #pragma unroll
        for (int hf = 0; hf < 2; hf++) {
            float mx = -1e30f;
            #pragma unroll
            for (int ni = 0; ni < 8; ni++)
                mx = fmaxf(mx, fmaxf(sacc[ni][hf * 2], sacc[ni][hf * 2 + 1]));
            mx = fmaxf(mx, __shfl_xor_sync(FULL, mx, 1));
            mx = fmaxf(mx, __shfl_xor_sync(FULL, mx, 2));
            const float mnew = fmaxf(mrow[hf], mx);
            const float alpha = ex2f(mrow[hf] - mnew);
            mrow[hf] = mnew;
            float sum = 0.f;
            #pragma unroll
            for (int ni = 0; ni < 8; ni++) {
                float p0 = ex2f(sacc[ni][hf * 2 + 0] - mnew);
                float p1 = ex2f(sacc[ni][hf * 2 + 1] - mnew);
                sacc[ni][hf * 2 + 0] = p0;
                sacc[ni][hf * 2 + 1] = p1;
                sum += p0 + p1;
            }
            sum += __shfl_xor_sync(FULL, sum, 1);
            sum += __shfl_xor_sync(FULL, sum, 2);
            lrow2[hf] = lrow2[hf] * alpha + sum;
            #pragma unroll
            for (int ni = 0; ni < 8; ni++) {
                oacc[ni][hf * 2 + 0] *= alpha;
                oacc[ni][hf * 2 + 1] *= alpha;
            }
        }

        // O += P @ V (score acc IS the A-fragment after key interleave)
        #pragma unroll
        for (int kk8 = 0; kk8 < 8; kk8++) {
            const int kc = kk8 * 8 + 2 * t;
            float a[4];
            a[0] = tf32_rn(sacc[kk8][0]);
            a[1] = tf32_rn(sacc[kk8][2]);
            a[2] = tf32_rn(sacc[kk8][1]);
            a[3] = tf32_rn(sacc[kk8][3]);
            #pragma unroll
            for (int ni = 0; ni < 8; ni++) {
                float2 vb2 = *(const float2*)&Vs[ni * 8 + g][kc];
                float b2[2] = {vb2.x, vb2.y};
                mma16n8k8(oacc[ni], a, b2);
            }
        }

        __syncthreads();
        if (j + 2 < NT) load_tile(j + 2, buf);
    }

    // epilogue: AO[b*S+s][h*64 + PERM8(d)] = tf32_rn(O / l)
    const int h = bh & (NH - 1);
    const int b = bh >> 4;
    const float inv0 = 1.0f / lrow2[0];
    const float inv1 = 1.0f / lrow2[1];
    const int r0 = q0 + mr + g;
    const int p0 = PERM8(2 * t);
    const int p1 = PERM8(2 * t + 1);
    #pragma unroll
    for (int ni = 0; ni < 8; ni++) {
        const int db = ni * 8;
        size_t i0 = ((size_t)(b * S_LEN + r0    )) * DMODEL + (size_t)(h * DK + db);
        size_t i1 = ((size_t)(b * S_LEN + r0 + 8)) * DMODEL + (size_t)(h * DK + db);
        AO[i0 + p0] = tf32_rn(oacc[ni][0] * inv0);
        AO[i0 + p1] = tf32_rn(oacc[ni][1] * inv0);
        AO[i1 + p0] = tf32_rn(oacc[ni][2] * inv1);
        AO[i1 + p1] = tf32_rn(oacc[ni][3] * inv1);
    }
}

// ---------------------------------------------------------------------------
extern "C" void kernel_launch(void* const* d_in, const int* in_sizes, int n_in,
                              void* d_out, int out_size)
{
    (void)in_sizes; (void)n_in; (void)out_size;
    const float* q  = (const float*)d_in[0];
    const float* k  = (const float*)d_in[1];
    const float* v  = (const float*)d_in[2];
    const float* Wq = (const float*)d_in[3];
    const float* bq = (const float*)d_in[4];
    const float* Wk = (const float*)d_in[5];
    const float* bk = (const float*)d_in[6];
    const float* Wv = (const float*)d_in[7];
    const float* bv = (const float*)d_in[8];
    const float* Wo = (const float*)d_in[9];
    const float* bo = (const float*)d_in[10];
    float* out = (float*)d_out;

    float *Qp, *Kp, *Vp, *AOp, *X0, *X1, *X2, *Wr;
    cudaGetSymbolAddress((void**)&Qp,  g_Q);
    cudaGetSymbolAddress((void**)&Kp,  g_K);
    cudaGetSymbolAddress((void**)&Vp,  g_V);
    cudaGetSymbolAddress((void**)&AOp, g_AO);
    cudaGetSymbolAddress((void**)&X0,  g_rX0);
    cudaGetSymbolAddress((void**)&X1,  g_rX1);
    cudaGetSymbolAddress((void**)&X2,  g_rX2);
    cudaGetSymbolAddress((void**)&Wr,  g_rW);
    float* W0 = Wr;
    float* W1 = Wr + (size_t)DMODEL * DMODEL;
    float* W2 = Wr + 2 * (size_t)DMODEL * DMODEL;
    float* W3 = Wr + 3 * (size_t)DMODEL * DMODEL;

    cudaFuncSetAttribute(gemm_mma_kernel,
                         cudaFuncAttributeMaxDynamicSharedMemorySize, GEMM_SMEM);
    cudaFuncSetAttribute(attn_mma_kernel,
                         cudaFuncAttributeMaxDynamicSharedMemorySize, ATT_SMEM);

    // prepass: round + k-permute activations (z=3) and weights (z=4)
    const int nX8 = (M_TOT * DMODEL) / 8;     // 1048576
    const int nW8 = (DMODEL * DMODEL) / 8;    // 131072
    prep_kernel<<<dim3((nX8 + 255) / 256, 1, 3), 256>>>(q, k, v, nullptr,
                                                        X0, X1, X2, nullptr, nX8);
    prep_kernel<<<dim3((nW8 + 255) / 256, 1, 4), 256>>>(Wq, Wk, Wv, Wo,
                                                        W0, W1, W2, W3, nW8);

    dim3 ggrid(DMODEL / 128, M_TOT / 128);   // (8, 64)
    gemm_mma_kernel<<<ggrid, 256, GEMM_SMEM>>>(X0, W0, bq, Qp, 0);
    gemm_mma_kernel<<<ggrid, 256, GEMM_SMEM>>>(X1, W1, bk, Kp, 0);
    gemm_mma_kernel<<<ggrid, 256, GEMM_SMEM>>>(X2, W2, bv, Vp, 2);

    attn_mma_kernel<<<dim3(S_LEN / 128, BATCH * NH), 256, ATT_SMEM>>>(AOp);

    gemm_mma_kernel<<<ggrid, 256, GEMM_SMEM>>>(AOp, W3, bo, out, 1);
}